// round 14
// baseline (speedup 1.0000x reference)
#include <cuda_runtime.h>
#include <cuda.h>
#include <cuda_bf16.h>
#include <math.h>
#include <stdint.h>

#define BB 8
#define LL 2048
#define CC 512
#define HH 8
#define HDIM 64
#define MH 2048
#define TOK (BB*LL)

#if defined(__CUDA_ARCH__) && (defined(__CUDA_ARCH_FEAT_SM103_ALL) || defined(__CUDA_ARCH_SPECIFIC__))
#define HAS_TCGEN05 1
#else
#define HAS_TCGEN05 0
#endif

// ---------------- scratch ---------------------------------------------------
__device__ __align__(1024) float g_x   [TOK*CC];
__device__ __align__(1024) float g_x2  [TOK*CC];
__device__ __align__(1024) float g_x3  [TOK*CC];
__device__ __align__(1024) __nv_bfloat16 g_ln  [TOK*CC];
__device__ __align__(1024) __nv_bfloat16 g_act [TOK*CC];
__device__ __align__(1024) __nv_bfloat16 g_xp  [TOK*CC];
__device__ __align__(1024) __nv_bfloat16 g_xp2 [TOK*CC];
__device__ __align__(1024) __nv_bfloat16 g_kv  [TOK*2*CC];
__device__ __align__(1024) __nv_bfloat16 g_q   [TOK*CC];
__device__ __align__(1024) __nv_bfloat16 g_xqr [TOK*CC];
__device__ __align__(1024) __nv_bfloat16 g_xab [TOK*CC];
__device__ __align__(1024) __nv_bfloat16 g_h1  [TOK*MH];
__device__ __align__(1024) __nv_bfloat16 g_wT  [3670016];
__device__ float g_kvpart[64*8*HDIM*HDIM];
__device__ float g_kspart[64*8*HDIM];
__device__ float g_kmean[BB*CC];
__device__ float g_kvmat[BB*HH*HDIM*HDIM];

#define WT_ACT 0
#define WT_IN  262144
#define WT_Q   524288
#define WT_KV  786432
#define WT_OUT 1310720
#define WT_FC1 1572864
#define WT_FC2 2621440

// ---------------- PTX helpers ---------------------------------------------
__device__ __forceinline__ uint32_t smem_u32(const void* p) {
    uint32_t a;
    asm("{ .reg .u64 t; cvta.to.shared.u64 t, %1; cvt.u32.u64 %0, t; }" : "=r"(a) : "l"(p));
    return a;
}
#define PKBF(res, lo, hi) \
    asm("cvt.rn.bf16x2.f32 %0, %1, %2;" : "=r"(res) : "f"(hi), "f"(lo))

__device__ __forceinline__ float4 ld_bf4(const __nv_bfloat16* p) {
    const uint2 u = *(const uint2*)p;
    const __nv_bfloat162 lo = *reinterpret_cast<const __nv_bfloat162*>(&u.x);
    const __nv_bfloat162 hi = *reinterpret_cast<const __nv_bfloat162*>(&u.y);
    const float2 f0 = __bfloat1622float2(lo);
    const float2 f1 = __bfloat1622float2(hi);
    return make_float4(f0.x, f0.y, f1.x, f1.y);
}

#define MBAR_INIT(a, c) \
    asm volatile("mbarrier.init.shared.b64 [%0], %1;" :: "r"(a), "r"(c) : "memory")
#define MBAR_EXPECT_TX(a, b) \
    asm volatile("mbarrier.arrive.expect_tx.shared.b64 _, [%0], %1;" :: "r"(a), "r"(b) : "memory")
#define MBAR_WAIT(a, ph) do { \
    asm volatile("{\n\t.reg .pred P;\n\tWL_%=:\n\t" \
        "mbarrier.try_wait.parity.acquire.cta.shared::cta.b64 P, [%0], %1, 0x989680;\n\t" \
        "@P bra.uni WD_%=;\n\tbra.uni WL_%=;\n\tWD_%=:\n\t}" \
        :: "r"(a), "r"(ph) : "memory"); } while (0)
#define TMA_LOAD2D(sm, mp, cx, cy, mb) \
    asm volatile("cp.async.bulk.tensor.2d.shared::cta.global.tile.mbarrier::complete_tx::bytes " \
        "[%0], [%1, {%2, %3}], [%4];" \
        :: "r"(sm), "l"(mp), "r"(cx), "r"(cy), "r"(mb) : "memory")

__device__ __forceinline__ void mma16n8k16bf(float* c, const uint32_t* a, const uint32_t* b) {
    asm volatile("mma.sync.aligned.m16n8k16.row.col.f32.bf16.bf16.f32 "
        "{%0,%1,%2,%3}, {%4,%5,%6,%7}, {%8,%9}, {%0,%1,%2,%3};"
        : "+f"(c[0]), "+f"(c[1]), "+f"(c[2]), "+f"(c[3])
        : "r"(a[0]), "r"(a[1]), "r"(a[2]), "r"(a[3]), "r"(b[0]), "r"(b[1]));
}

#if HAS_TCGEN05
#define TC_ALLOC(sm, n) \
    asm volatile("tcgen05.alloc.cta_group::1.sync.aligned.shared::cta.b32 [%0], %1;" :: "r"(sm), "r"(n) : "memory")
#define TC_DEALLOC(t, n) \
    asm volatile("tcgen05.dealloc.cta_group::1.sync.aligned.b32 %0, %1;" :: "r"(t), "r"(n))
#define TC_RELINQ() \
    asm volatile("tcgen05.relinquish_alloc_permit.cta_group::1.sync.aligned;")
#define TC_COMMIT(mb) \
    asm volatile("tcgen05.commit.cta_group::1.mbarrier::arrive::one.shared::cluster.b64 [%0];" :: "r"(mb) : "memory")
#define TC_FENCE_AFTER()  asm volatile("tcgen05.fence::after_thread_sync;" ::: "memory")
#define TC_FENCE_BEFORE() asm volatile("tcgen05.fence::before_thread_sync;" ::: "memory")
#define TC_WAIT_LD()      asm volatile("tcgen05.wait::ld.sync.aligned;" ::: "memory")
#define TC_LD32(r, ta) \
    asm volatile("tcgen05.ld.sync.aligned.32x32b.x32.b32 " \
        "{%0,%1,%2,%3,%4,%5,%6,%7,%8,%9,%10,%11,%12,%13,%14,%15," \
        "%16,%17,%18,%19,%20,%21,%22,%23,%24,%25,%26,%27,%28,%29,%30,%31}, [%32];" \
        : "=r"((r)[0]),"=r"((r)[1]),"=r"((r)[2]),"=r"((r)[3]),"=r"((r)[4]),"=r"((r)[5]), \
          "=r"((r)[6]),"=r"((r)[7]),"=r"((r)[8]),"=r"((r)[9]),"=r"((r)[10]),"=r"((r)[11]), \
          "=r"((r)[12]),"=r"((r)[13]),"=r"((r)[14]),"=r"((r)[15]),"=r"((r)[16]),"=r"((r)[17]), \
          "=r"((r)[18]),"=r"((r)[19]),"=r"((r)[20]),"=r"((r)[21]),"=r"((r)[22]),"=r"((r)[23]), \
          "=r"((r)[24]),"=r"((r)[25]),"=r"((r)[26]),"=r"((r)[27]),"=r"((r)[28]),"=r"((r)[29]), \
          "=r"((r)[30]),"=r"((r)[31]) : "r"(ta))

__device__ __forceinline__ void mma_bf16_ss(uint32_t d, uint64_t ad, uint64_t bd,
                                            uint32_t idesc, uint32_t en) {
    asm volatile("{\n\t.reg .pred p;\n\tsetp.ne.u32 p, %5, 0;\n\t"
        "tcgen05.mma.cta_group::1.kind::f16 [%0], %1, %2, %3, {%4, %4, %4, %4}, p;\n\t}"
        :: "r"(d), "l"(ad), "l"(bd), "r"(idesc), "r"(0u), "r"(en) : "memory");
}
#endif

#define DESC_SW128 ((2ull << 61) | (1ull << 46) | (64ull << 32) | (1ull << 16))
#define MK_DESC(a)  (DESC_SW128 | (((uint64_t)((a) >> 4)) & 0x3FFF))
// idesc kind::f16 bf16: N=128 -> 16<<17, M=128 -> 8<<24
#define IDESC_BF16 ((1u << 4) | (1u << 7) | (1u << 10) | (16u << 17) | (8u << 24))

// EPI: 0 none, 2 elu+1, 3 gelu, 4 elu+1 on cols<N/2, 5 merged silu/none
template<int EPI>
__device__ __forceinline__ float epi_fn(float v, int gcol, int N, bool silu5) {
    if (EPI == 2) v = (v > 0.f) ? v + 1.f : __expf(v);
    else if (EPI == 3) v = 0.5f * v * (1.f + erff(v * 0.70710678118654752f));
    else if (EPI == 4) { if (gcol < (N >> 1)) v = (v > 0.f) ? v + 1.f : __expf(v); }
    else if (EPI == 5) { if (silu5) v = v / (1.f + __expf(-v)); }
    return v;
}

__device__ __forceinline__ uint32_t swzb(int r, int c) {
    const uint32_t off = (uint32_t)(r * 128 + c * 2);
    return off ^ ((off >> 3) & 0x70);
}

// ---- tensor-core GEMM, 128x128 tile, bf16, 2-stage ring, 3 CTAs/SM --------
#define TN 128
#define SM_TMEMP 0
#define SM_FULLB(i) (8 + 8*(i))
#define SM_DONEB(i) (24 + 8*(i))
#define SM_FINAL 40
#define SM_STG 1024
#define STG_SZ 32768
#define SM_SZ (1024 + 2*STG_SZ)

// OBF: output stored as bf16 (out ptr reinterpreted)
template<int EPI, bool RES, bool OBF>
__global__ __launch_bounds__(256, 3) void tc_gemm(
    const __grid_constant__ CUtensorMap tmA,
    const __grid_constant__ CUtensorMap tmB,
    const float* __restrict__ bias, const float* __restrict__ bias2,
    const float* __restrict__ res,
    float* __restrict__ out, float* __restrict__ out2, int N, int K)
{
    extern __shared__ char smem[];
    const uint32_t sb = smem_u32(smem);
    const int tid = threadIdx.x;
    const int wid = tid >> 5, lane = tid & 31;
    const int bx = blockIdx.x, by = blockIdx.y;
    const int nK = K >> 6;

    float* op = out;
    const float* bp = bias;
    int colb = bx * TN;
    bool silu5 = false;
    if (EPI == 5) {
        const int hx = gridDim.x >> 1;
        if (bx < hx) silu5 = true;
        else { op = out2; bp = bias2; colb = (bx - hx) * TN; }
    }

#if HAS_TCGEN05
    if (tid == 0) {
#pragma unroll
        for (int i = 0; i < 2; i++) { MBAR_INIT(sb + SM_FULLB(i), 1); MBAR_INIT(sb + SM_DONEB(i), 1); }
        MBAR_INIT(sb + SM_FINAL, 1);
    }
    if (wid == 0) { TC_ALLOC(sb + SM_TMEMP, 128); TC_RELINQ(); }
    __syncthreads();
    uint32_t tmem;
    asm volatile("ld.shared.b32 %0, [%1];" : "=r"(tmem) : "r"(sb + SM_TMEMP));

    if (tid == 0) {
        int phd[2] = { 0, 0 };
        for (int kt = 0; kt < nK; kt++) {
            const int buf = kt & 1;
            if (kt >= 2) { MBAR_WAIT(sb + SM_DONEB(buf), phd[buf]); phd[buf] ^= 1; }
            MBAR_EXPECT_TX(sb + SM_FULLB(buf), 32768u);
            const uint32_t st = sb + SM_STG + buf * STG_SZ;
            TMA_LOAD2D(st,         &tmA, kt * 64, by * 128, sb + SM_FULLB(buf));
            TMA_LOAD2D(st + 16384, &tmB, kt * 64, bx * TN, sb + SM_FULLB(buf));
        }
    } else if (tid == 32) {
        int phf[2] = { 0, 0 };
        for (int kt = 0; kt < nK; kt++) {
            const int buf = kt & 1;
            MBAR_WAIT(sb + SM_FULLB(buf), phf[buf]); phf[buf] ^= 1;
            const uint32_t st = sb + SM_STG + buf * STG_SZ;
            const uint64_t ad = MK_DESC(st);
            const uint64_t bd = MK_DESC(st + 16384);
#pragma unroll
            for (int s = 0; s < 4; s++)
                mma_bf16_ss(tmem, ad + s * 2, bd + s * 2, IDESC_BF16,
                            (kt > 0 || s > 0) ? 1u : 0u);
            TC_COMMIT(sb + SM_DONEB(buf));
        }
        TC_COMMIT(sb + SM_FINAL);
    }

    MBAR_WAIT(sb + SM_FINAL, 0);
    TC_FENCE_AFTER();

    // epilogue: 8 warps; warp w: subpartition w&3, col chunks (w>>2)*2 + h
    const int row = by * 128 + (wid & 3) * 32 + lane;
#pragma unroll
    for (int h = 0; h < 2; h++) {
        const int cc = (wid >> 2) * 2 + h;
        uint32_t r[32];
        TC_LD32(r, tmem + cc * 32);
        TC_WAIT_LD();
        const int col = colb + cc * 32;
        const size_t o = (size_t)row * N + col;
        float vbuf[32];
#pragma unroll
        for (int j = 0; j < 32; j++) {
            float v = __uint_as_float(r[j]) + bp[col + j];
            v = epi_fn<EPI>(v, col + j, N, silu5);
            if (RES) v += res[o + j];
            vbuf[j] = v;
        }
        if (OBF) {
            uint32_t pk[16];
#pragma unroll
            for (int j = 0; j < 16; j++) PKBF(pk[j], vbuf[2 * j], vbuf[2 * j + 1]);
            uint4* dst = (uint4*)((__nv_bfloat16*)op + o);
#pragma unroll
            for (int j = 0; j < 4; j++)
                dst[j] = make_uint4(pk[4 * j], pk[4 * j + 1], pk[4 * j + 2], pk[4 * j + 3]);
        } else {
#pragma unroll
            for (int j = 0; j < 8; j++)
                *(float4*)(op + o + j * 4) = *(float4*)(&vbuf[j * 4]);
        }
    }
    TC_FENCE_BEFORE();
    __syncthreads();
    if (wid == 0) TC_DEALLOC(tmem, 128);

#else
    // fallback: mma.sync bf16 m16n8k16, single stage
    if (tid == 0) MBAR_INIT(sb + SM_FULLB(0), 1);
    __syncthreads();

    const char* As = smem + SM_STG;
    const char* Bs = smem + SM_STG + 16384;
    const int wm = wid >> 2;
    const int wn = wid & 3;
    int ph = 0;

    float c[4][4][4];
#pragma unroll
    for (int i = 0; i < 4; i++)
#pragma unroll
        for (int j = 0; j < 4; j++)
#pragma unroll
            for (int q = 0; q < 4; q++) c[i][j][q] = 0.f;

    for (int kt = 0; kt < nK; kt++) {
        __syncthreads();
        if (tid == 0) {
            MBAR_EXPECT_TX(sb + SM_FULLB(0), 32768u);
            TMA_LOAD2D(sb + SM_STG,         &tmA, kt * 64, by * 128, sb + SM_FULLB(0));
            TMA_LOAD2D(sb + SM_STG + 16384, &tmB, kt * 64, bx * TN, sb + SM_FULLB(0));
        }
        MBAR_WAIT(sb + SM_FULLB(0), ph); ph ^= 1;

#pragma unroll
        for (int s = 0; s < 4; s++) {
            const int k0 = s * 16;
            uint32_t af[4][4];
#pragma unroll
            for (int i = 0; i < 4; i++) {
                const int r0 = wm * 64 + i * 16 + (lane >> 2);
                af[i][0] = *(const uint32_t*)(As + swzb(r0,     k0 + 2 * (lane & 3)));
                af[i][1] = *(const uint32_t*)(As + swzb(r0 + 8, k0 + 2 * (lane & 3)));
                af[i][2] = *(const uint32_t*)(As + swzb(r0,     k0 + 8 + 2 * (lane & 3)));
                af[i][3] = *(const uint32_t*)(As + swzb(r0 + 8, k0 + 8 + 2 * (lane & 3)));
            }
            uint32_t bf[4][2];
#pragma unroll
            for (int j = 0; j < 4; j++) {
                const int n = wn * 32 + j * 8 + (lane >> 2);
                bf[j][0] = *(const uint32_t*)(Bs + swzb(n, k0 + 2 * (lane & 3)));
                bf[j][1] = *(const uint32_t*)(Bs + swzb(n, k0 + 8 + 2 * (lane & 3)));
            }
#pragma unroll
            for (int i = 0; i < 4; i++)
#pragma unroll
                for (int j = 0; j < 4; j++)
                    mma16n8k16bf(c[i][j], af[i], bf[j]);
        }
    }

#pragma unroll
    for (int i = 0; i < 4; i++) {
        const int r0 = by * 128 + wm * 64 + i * 16 + (lane >> 2);
#pragma unroll
        for (int j = 0; j < 4; j++) {
            const int cn = colb + wn * 32 + j * 8 + 2 * (lane & 3);
#pragma unroll
            for (int q = 0; q < 4; q++) {
                const int rr = r0 + (q >> 1) * 8;
                const int gc = cn + (q & 1);
                const size_t o = (size_t)rr * N + gc;
                float v = c[i][j][q] + bp[gc];
                v = epi_fn<EPI>(v, gc, N, silu5);
                if (RES) v += res[o];
                if (OBF) ((__nv_bfloat16*)op)[o] = __float2bfloat16(v);
                else op[o] = v;
            }
        }
    }
#endif
}

// ---------------- fused prep: 7 weight transposes (->bf16) + x_q round -----
#define ROUND_BLKS 8192
struct PrepTab {
    const float* src[7];
    int dst[7];
    int K[7];
    int N[7];
    int boff[8];
};

__global__ void prep_kernel(const __grid_constant__ PrepTab tab,
                            const float* __restrict__ xq,
                            __nv_bfloat16* __restrict__ xqr,
                            __nv_bfloat16* __restrict__ wT)
{
    const int bid = blockIdx.x;
    const int tid = threadIdx.x;
    if (bid < ROUND_BLKS) {
        const int idx = bid * 1024 + tid * 4;
        const float4 v = *(const float4*)(xq + idx);
        uint32_t p0, p1;
        PKBF(p0, v.x, v.y);
        PKBF(p1, v.z, v.w);
        *(uint2*)(xqr + idx) = make_uint2(p0, p1);
        return;
    }
    const int rb = bid - ROUND_BLKS;
    int i = 0;
#pragma unroll
    for (int s = 1; s < 7; s++) if (rb >= tab.boff[s]) i = s;
    const int local = rb - tab.boff[i];
    const int K = tab.K[i], N = tab.N[i];
    const int nbx = N >> 5;
    const int n0 = (local % nbx) * 32;
    const int k0 = (local / nbx) * 32;
    const float* in = tab.src[i];
    __nv_bfloat16* out = wT + tab.dst[i];

    __shared__ float t[32][33];
    const int tx = tid & 31, ty = tid >> 5;
#pragma unroll
    for (int it = 0; it < 4; it++)
        t[ty + it * 8][tx] = in[(size_t)(k0 + ty + it * 8) * N + n0 + tx];
    __syncthreads();
#pragma unroll
    for (int it = 0; it < 4; it++)
        out[(size_t)(n0 + ty + it * 8) * K + k0 + tx] = __float2bfloat16(t[tx][ty + it * 8]);
}

// --------- fused cpe conv + LayerNorm (LN out -> bf16) ---------------------
__global__ void cpe_ln_kernel(const float* __restrict__ x,
                              const float* __restrict__ w,
                              const float* __restrict__ cb,
                              const float* __restrict__ g,
                              const float* __restrict__ b,
                              float* __restrict__ xout,
                              __nv_bfloat16* __restrict__ lnout)
{
    const int row = blockIdx.x;
    const int l = row & (LL - 1);
    const int tid = threadIdx.x;
    const int c0 = tid * 4;

    const float4 vm = ((const float4*)(x + (size_t)row * CC))[tid];
    float4 vp = make_float4(0.f, 0.f, 0.f, 0.f);
    float4 vn = make_float4(0.f, 0.f, 0.f, 0.f);
    if (l > 0)      vp = ((const float4*)(x + (size_t)(row - 1) * CC))[tid];
    if (l < LL - 1) vn = ((const float4*)(x + (size_t)(row + 1) * CC))[tid];

    const float xm[4] = { vm.x, vm.y, vm.z, vm.w };
    const float xpv[4] = { vp.x, vp.y, vp.z, vp.w };
    const float xnv[4] = { vn.x, vn.y, vn.z, vn.w };
    float o[4];
#pragma unroll
    for (int j = 0; j < 4; j++) {
        const int c = c0 + j;
        float s = cb[c] + w[c * 3 + 0] * xpv[j] + w[c * 3 + 1] * xm[j]
                        + w[c * 3 + 2] * xnv[j];
        o[j] = xm[j] + s;
    }
    *(float4*)(xout + (size_t)row * CC + c0) = *(float4*)o;

    float s  = o[0] + o[1] + o[2] + o[3];
    float sq = o[0]*o[0] + o[1]*o[1] + o[2]*o[2] + o[3]*o[3];
#pragma unroll
    for (int of = 16; of; of >>= 1) {
        s  += __shfl_xor_sync(0xffffffffu, s,  of);
        sq += __shfl_xor_sync(0xffffffffu, sq, of);
    }
    __shared__ float ssum[4], ssq[4];
    const int wd = tid >> 5;
    if ((tid & 31) == 0) { ssum[wd] = s; ssq[wd] = sq; }
    __syncthreads();
    const float tot  = ssum[0] + ssum[1] + ssum[2] + ssum[3];
    const float totq = ssq[0]  + ssq[1]  + ssq[2]  + ssq[3];
    const float mu  = tot * (1.f / CC);
    const float var = totq * (1.f / CC) - mu * mu;
    const float rs  = rsqrtf(var + 1e-5f);
    float ov[4];
#pragma unroll
    for (int j = 0; j < 4; j++)
        ov[j] = (o[j] - mu) * rs * g[c0 + j] + b[c0 + j];
    uint32_t p0, p1;
    PKBF(p0, ov[0], ov[1]);
    PKBF(p1, ov[2], ov[3]);
    *(uint2*)(lnout + (size_t)row * CC + c0) = make_uint2(p0, p1);
}

// --------- dwc (reshaped view, bf16 in), silu -> bf16, x4 ------------------
__global__ void dwc_kernel(const __nv_bfloat16* __restrict__ in,
                           const float* __restrict__ w,
                           const float* __restrict__ bias,
                           __nv_bfloat16* __restrict__ out)
{
    const int t = blockIdx.x * blockDim.x + threadIdx.x;
    const int idx = t * 4;
    const int f = idx & (LL * CC - 1);
    const int r = f >> 11;
    const int j0 = f & (LL - 1);
    const float4 v = ld_bf4(in + idx);
    const float w0 = w[r * 3], w1 = w[r * 3 + 1], w2 = w[r * 3 + 2], bb = bias[r];
    float a[6];
    a[0] = (j0 > 0) ? __bfloat162float(in[idx - 1]) : 0.f;
    a[1] = v.x; a[2] = v.y; a[3] = v.z; a[4] = v.w;
    a[5] = (j0 + 4 < LL) ? __bfloat162float(in[idx + 4]) : 0.f;
    float o[4];
#pragma unroll
    for (int jj = 0; jj < 4; jj++) {
        const int j = j0 + jj;
        float s = bb + w1 * a[jj + 1];
        if (j > 0)      s += w0 * a[jj];
        if (j < LL - 1) s += w2 * a[jj + 2];
        o[jj] = s / (1.f + __expf(-s));
    }
    uint32_t p0, p1;
    PKBF(p0, o[0], o[1]);
    PKBF(p1, o[2], o[3]);
    *(uint2*)(out + idx) = make_uint2(p0, p1);
}

// --------- kv partial: K^T V (64x64) + k colsum (kv bf16) -------------------
__global__ __launch_bounds__(256) void kvp_kernel(const __nv_bfloat16* __restrict__ kv,
                                                  float* __restrict__ kvpart,
                                                  float* __restrict__ kspart)
{
    const int chunk = blockIdx.x;
    const int bh = blockIdx.y;
    const int b = bh >> 3, h = bh & 7;
    __shared__ float ks[64][64];
    __shared__ float vs[64][64];
    const int tid = threadIdx.x;
    const int d0 = (tid >> 4) << 2, e0 = (tid & 15) << 2;
    float acc[4][4];
#pragma unroll
    for (int i = 0; i < 4; i++)
#pragma unroll
        for (int j = 0; j < 4; j++) acc[i][j] = 0.f;
    float ksum = 0.f;

    const __nv_bfloat16* kb = kv + (size_t)b * LL * (2 * CC) + h * HDIM;
    const __nv_bfloat16* vb = kb + CC;
    const int row0 = chunk * 256;
    for (int n0 = row0; n0 < row0 + 256; n0 += 64) {
#pragma unroll
        for (int i = 0; i < 4; i++) {
            int v = tid + i * 256;
            int r = v >> 4; int c = (v & 15) << 2;
            *(float4*)(&ks[r][c]) = ld_bf4(kb + (size_t)(n0 + r) * (2 * CC) + c);
            *(float4*)(&vs[r][c]) = ld_bf4(vb + (size_t)(n0 + r) * (2 * CC) + c);
        }
        __syncthreads();
        if (tid < 64) {
            float s = 0.f;
#pragma unroll 16
            for (int n = 0; n < 64; n++) s += ks[n][tid];
            ksum += s;
        }
#pragma unroll 8
        for (int n = 0; n < 64; n++) {
            float a[4], bb[4];
            *(float4*)a  = *(float4*)(&ks[n][d0]);
            *(float4*)bb = *(float4*)(&vs[n][e0]);
#pragma unroll
            for (int i = 0; i < 4; i++)
#pragma unroll
                for (int j = 0; j < 4; j++)
                    acc[i][j] = fmaf(a[i], bb[j], acc[i][j]);
        }
        __syncthreads();
    }
    float* o = kvpart + ((size_t)bh * 8 + chunk) * (HDIM * HDIM);
#pragma unroll
    for (int i = 0; i < 4; i++)
#pragma unroll
        for (int j = 0; j < 4; j++)
            o[(d0 + i) * HDIM + e0 + j] = acc[i][j];
    if (tid < 64) kspart[((size_t)bh * 8 + chunk) * HDIM + tid] = ksum;
}

__global__ void kvred_kernel(const float* __restrict__ kvpart,
                             const float* __restrict__ kspart,
                             float* __restrict__ kvmat,
                             float* __restrict__ kmean)
{
    const int bh = blockIdx.x;
    const int tid = threadIdx.x;
#pragma unroll
    for (int i = 0; i < 16; i++) {
        const int e = i * 256 + tid;
        float s = 0.f;
#pragma unroll
        for (int c = 0; c < 8; c++)
            s += kvpart[((size_t)bh * 8 + c) * (HDIM * HDIM) + e];
        kvmat[(size_t)bh * (HDIM * HDIM) + e] = s * (1.f / LL);
    }
    if (tid < 64) {
        float s = 0.f;
#pragma unroll
        for (int c = 0; c < 8; c++)
            s += kspart[((size_t)bh * 8 + c) * HDIM + tid];
        kmean[(size_t)(bh >> 3) * CC + (bh & 7) * HDIM + tid] = s;
    }
}

// --------- attention out, FUSED with lepe conv + act gate -> xab bf16 ------
__global__ __launch_bounds__(256) void attn_kernel(
    const __nv_bfloat16* __restrict__ q,
    const float* __restrict__ kvmat,
    const float* __restrict__ kmean,
    const __nv_bfloat16* __restrict__ kv,
    const __nv_bfloat16* __restrict__ act,
    const float* __restrict__ lw,
    const float* __restrict__ lb,
    __nv_bfloat16* __restrict__ xab)
{
    const int n0 = blockIdx.x * 64;
    const int h = blockIdx.y, b = blockIdx.z;
    __shared__ float kvm[64][64];
    __shared__ float qT[64][65];
    __shared__ float km[64];
    __shared__ float zs[64];
    const int tid = threadIdx.x;

    const float* kvb = kvmat + ((size_t)(b * HH + h)) * (HDIM * HDIM);
#pragma unroll
    for (int i = 0; i < 4; i++) {
        int v = tid + i * 256;
        int r = v >> 4; int c = (v & 15) << 2;
        *(float4*)(&kvm[r][c]) = *(const float4*)(kvb + (size_t)r * 64 + c);
    }
    const __nv_bfloat16* qb = q + (size_t)b * LL * CC + (size_t)n0 * CC + h * HDIM;
#pragma unroll
    for (int i = 0; i < 4; i++) {
        int v = tid + i * 256;
        int t = v >> 4; int c = (v & 15) << 2;
        float4 q4 = ld_bf4(qb + (size_t)t * CC + c);
        qT[c + 0][t] = q4.x; qT[c + 1][t] = q4.y;
        qT[c + 2][t] = q4.z; qT[c + 3][t] = q4.w;
    }
    if (tid < 64) km[tid] = kmean[(size_t)b * CC + h * HDIM + tid] * (1.f / LL);
    __syncthreads();
    if (tid < 64) {
        float dot = 0.f;
#pragma unroll 16
        for (int d = 0; d < 64; d++) dot += qT[d][tid] * km[d];
        zs[tid] = 1.f / (dot + 1e-6f);
    }
    __syncthreads();

    const int t0 = (tid >> 4) << 2, e0 = (tid & 15) << 2;
    float acc[4][4];
#pragma unroll
    for (int i = 0; i < 4; i++)
#pragma unroll
        for (int j = 0; j < 4; j++) acc[i][j] = 0.f;
#pragma unroll 8
    for (int d = 0; d < 64; d++) {
        float a[4];
#pragma unroll
        for (int i = 0; i < 4; i++) a[i] = qT[d][t0 + i];
        float bb[4];
        *(float4*)bb = *(float4*)(&kvm[d][e0]);
#pragma unroll
        for (int i = 0; i < 4; i++)
#pragma unroll
            for (int j = 0; j < 4; j++)
                acc[i][j] = fmaf(a[i], bb[j], acc[i][j]);
    }

    const int gc0 = h * HDIM + e0;
    float w0[4], w1[4], w2[4], lb4[4];
#pragma unroll
    for (int j = 0; j < 4; j++) {
        w0[j]  = lw[(gc0 + j) * 3 + 0];
        w1[j]  = lw[(gc0 + j) * 3 + 1];
        w2[j]  = lw[(gc0 + j) * 3 + 2];
        lb4[j] = lb[gc0 + j];
    }
#pragma unroll
    for (int i = 0; i < 4; i++) {
        const int n = n0 + t0 + i;
        const size_t gn = (size_t)b * LL + n;
        const __nv_bfloat16* vr = kv + gn * (2 * CC) + CC + gc0;
        const float4 vmv = ld_bf4(vr);
        float4 vpv = make_float4(0.f, 0.f, 0.f, 0.f);
        float4 vnv = make_float4(0.f, 0.f, 0.f, 0.f);
        if (n > 0)      vpv = ld_bf4(vr - 2 * CC);
        if (n < LL - 1) vnv = ld_bf4(vr + 2 * CC);
        const float4 a4 = ld_bf4(act + gn * CC + gc0);
        const float z = zs[t0 + i];
        float o[4];
        o[0] = (acc[i][0] * z + lb4[0] + w0[0] * vpv.x + w1[0] * vmv.x + w2[0] * vnv.x) * a4.x;
        o[1] = (acc[i][1] * z + lb4[1] + w0[1] * vpv.y + w1[1] * vmv.y + w2[1] * vnv.y) * a4.y;
        o[2] = (acc[i][2] * z + lb4[2] + w0[2] * vpv.z + w1[2] * vmv.z + w2[2] * vnv.z) * a4.z;
        o[3] = (acc[i][3] * z + lb4[3] + w0[3] * vpv.w + w1[3] * vmv.w + w2[3] * vnv.w) * a4.w;
        uint32_t p0, p1;
        PKBF(p0, o[0], o[1]);
        PKBF(p1, o[2], o[3]);
        *(uint2*)(xab + gn * CC + gc0) = make_uint2(p0, p1);
    }
}

// ---------------------------------------------------------------------------
typedef CUresult (*PFN_encodeTiled)(CUtensorMap*, CUtensorMapDataType, cuuint32_t,
    void*, const cuuint64_t*, const cuuint64_t*, const cuuint32_t*, const cuuint32_t*,
    CUtensorMapInterleave, CUtensorMapSwizzle, CUtensorMapL2promotion, CUtensorMapFloatOOBfill);

static void mk2db(PFN_encodeTiled fn, CUtensorMap* m, const void* p,
                  unsigned long long inner, unsigned long long outer, unsigned boxY)
{
    cuuint64_t dims[2] = { inner, outer };
    cuuint64_t st[1]   = { inner * 2 };
    cuuint32_t box[2]  = { 64, boxY };
    cuuint32_t es[2]   = { 1, 1 };
    fn(m, CU_TENSOR_MAP_DATA_TYPE_BFLOAT16, 2, (void*)p, dims, st, box, es,
       CU_TENSOR_MAP_INTERLEAVE_NONE, CU_TENSOR_MAP_SWIZZLE_128B,
       CU_TENSOR_MAP_L2_PROMOTION_L2_128B, CU_TENSOR_MAP_FLOAT_OOB_FILL_NONE);
}

extern "C" void kernel_launch(void* const* d_in, const int* in_sizes, int n_in,
                              void* d_out, int out_size)
{
    const float* x_q    = (const float*)d_in[0];
    const float* x_kv   = (const float*)d_in[1];
    const float* cpe1_w = (const float*)d_in[2];
    const float* cpe1_b = (const float*)d_in[3];
    const float* n1_g   = (const float*)d_in[4];
    const float* n1_b   = (const float*)d_in[5];
    const float* in_w   = (const float*)d_in[6];
    const float* in_b   = (const float*)d_in[7];
    const float* act_w  = (const float*)d_in[8];
    const float* act_b  = (const float*)d_in[9];
    const float* dwc_w  = (const float*)d_in[10];
    const float* dwc_b  = (const float*)d_in[11];
    const float* q_w    = (const float*)d_in[12];
    const float* q_b    = (const float*)d_in[13];
    const float* kv_w   = (const float*)d_in[14];
    const float* kv_b   = (const float*)d_in[15];
    const float* lepe_w = (const float*)d_in[16];
    const float* lepe_b = (const float*)d_in[17];
    const float* out_w  = (const float*)d_in[18];
    const float* out_b  = (const float*)d_in[19];
    const float* cpe2_w = (const float*)d_in[20];
    const float* cpe2_b = (const float*)d_in[21];
    const float* n2_g   = (const float*)d_in[22];
    const float* n2_b   = (const float*)d_in[23];
    const float* fc1_w  = (const float*)d_in[24];
    const float* fc1_b  = (const float*)d_in[25];
    const float* fc2_w  = (const float*)d_in[26];
    const float* fc2_b  = (const float*)d_in[27];
    float* outp = (float*)d_out;

    float *p_x, *p_x2, *p_x3, *p_kvpart, *p_kspart, *p_kmean, *p_kvmat;
    __nv_bfloat16 *p_ln, *p_act, *p_xp, *p_xp2, *p_kv, *p_q, *p_xqr, *p_xab, *p_h1, *p_wT;
    cudaGetSymbolAddress((void**)&p_x,      g_x);
    cudaGetSymbolAddress((void**)&p_x2,     g_x2);
    cudaGetSymbolAddress((void**)&p_x3,     g_x3);
    cudaGetSymbolAddress((void**)&p_ln,     g_ln);
    cudaGetSymbolAddress((void**)&p_act,    g_act);
    cudaGetSymbolAddress((void**)&p_xp,     g_xp);
    cudaGetSymbolAddress((void**)&p_xp2,    g_xp2);
    cudaGetSymbolAddress((void**)&p_kv,     g_kv);
    cudaGetSymbolAddress((void**)&p_q,      g_q);
    cudaGetSymbolAddress((void**)&p_xqr,    g_xqr);
    cudaGetSymbolAddress((void**)&p_xab,    g_xab);
    cudaGetSymbolAddress((void**)&p_h1,     g_h1);
    cudaGetSymbolAddress((void**)&p_wT,     g_wT);
    cudaGetSymbolAddress((void**)&p_kvpart, g_kvpart);
    cudaGetSymbolAddress((void**)&p_kspart, g_kspart);
    cudaGetSymbolAddress((void**)&p_kmean,  g_kmean);
    cudaGetSymbolAddress((void**)&p_kvmat,  g_kvmat);

    PFN_encodeTiled enc = nullptr;
#if CUDART_VERSION >= 12050
    {
        cudaDriverEntryPointQueryResult qr;
        cudaGetDriverEntryPointByVersion("cuTensorMapEncodeTiled", (void**)&enc,
                                         12000, cudaEnableDefault, &qr);
    }
#else
    {
        cudaDriverEntryPointQueryResult qr;
        cudaGetDriverEntryPoint("cuTensorMapEncodeTiled", (void**)&enc,
                                cudaEnableDefault, &qr);
    }
#endif

    CUtensorMap tmLn, tmXqr, tmXp2, tmXab, tmH1;
    CUtensorMap tmWai, tmWq, tmWkv, tmWout, tmWfc1, tmWfc2;
    mk2db(enc, &tmLn,  p_ln,  CC, TOK, 128);
    mk2db(enc, &tmXqr, p_xqr, CC, TOK, 128);
    mk2db(enc, &tmXp2, p_xp2, CC, TOK, 128);
    mk2db(enc, &tmXab, p_xab, CC, TOK, 128);
    mk2db(enc, &tmH1,  p_h1,  MH, TOK, 128);
    mk2db(enc, &tmWai,  p_wT + WT_ACT, CC, 2 * CC, 128);
    mk2db(enc, &tmWq,   p_wT + WT_Q,   CC, CC,     128);
    mk2db(enc, &tmWkv,  p_wT + WT_KV,  CC, 2 * CC, 128);
    mk2db(enc, &tmWout, p_wT + WT_OUT, CC, CC,     128);
    mk2db(enc, &tmWfc1, p_wT + WT_FC1, CC, MH,     128);
    mk2db(enc, &tmWfc2, p_wT + WT_FC2, MH, CC,     128);

    cudaFuncSetAttribute(tc_gemm<5, false, true >, cudaFuncAttributeMaxDynamicSharedMemorySize, SM_SZ);
    cudaFuncSetAttribute(tc_gemm<4, false, true >, cudaFuncAttributeMaxDynamicSharedMemorySize, SM_SZ);
    cudaFuncSetAttribute(tc_gemm<2, false, true >, cudaFuncAttributeMaxDynamicSharedMemorySize, SM_SZ);
    cudaFuncSetAttribute(tc_gemm<0, true,  false>, cudaFuncAttributeMaxDynamicSharedMemorySize, SM_SZ);
    cudaFuncSetAttribute(tc_gemm<3, false, true >, cudaFuncAttributeMaxDynamicSharedMemorySize, SM_SZ);

    const int M = TOK;
    const int VEC_BLOCKS = (TOK * CC / 4) / 256;
    const dim3 G4(4, M / 128), G8(8, M / 128), G16(16, M / 128);

    // fused prep: 7 transposes (->bf16) + x_q round
    PrepTab tab;
    const float* srcs[7] = { act_w, in_w, q_w, kv_w, out_w, fc1_w, fc2_w };
    const int dsts[7] = { WT_ACT, WT_IN, WT_Q, WT_KV, WT_OUT, WT_FC1, WT_FC2 };
    const int Ks[7] = { CC, CC, CC, CC, CC, CC, MH };
    const int Ns[7] = { CC, CC, CC, 2*CC, CC, MH, CC };
    int off = 0;
    for (int i = 0; i < 7; i++) {
        tab.src[i] = srcs[i]; tab.dst[i] = dsts[i];
        tab.K[i] = Ks[i]; tab.N[i] = Ns[i];
        tab.boff[i] = off;
        off += (Ns[i] >> 5) * (Ks[i] >> 5);
    }
    tab.boff[7] = off;
    prep_kernel<<<ROUND_BLKS + off, 256>>>(tab, x_q, p_xqr, p_wT);

    // 1+2. x = x_kv + cpe1(x_kv); ln = LN1(x) (bf16)
    cpe_ln_kernel<<<TOK, 128>>>(x_kv, cpe1_w, cpe1_b, n1_g, n1_b, p_x, p_ln);
    // 3. q = bf16(elu(x_q @ q_w + b) + 1)
    tc_gemm<2, false, true><<<G4, 256, SM_SZ>>>(tmXqr, tmWq, q_b, nullptr, nullptr, (float*)p_q, nullptr, CC, CC);
    // 4+5. act = bf16(silu(ln@act_w+b)) ; xp = bf16(ln@in_w+b)
    tc_gemm<5, false, true><<<G8, 256, SM_SZ>>>(tmLn, tmWai, act_b, in_b, nullptr, (float*)p_act, (float*)p_xp, CC, CC);
    // 6. xp2 = bf16(silu(dwconv(reshape(xp))))
    dwc_kernel<<<VEC_BLOCKS, 256>>>(p_xp, dwc_w, dwc_b, p_xp2);
    // 7. kv = bf16(xp2 @ kv_w + b); elu+1 on k half
    tc_gemm<4, false, true><<<G8, 256, SM_SZ>>>(tmXp2, tmWkv, kv_b, nullptr, nullptr, (float*)p_kv, nullptr, 2 * CC, CC);
    // 8+9. kv_mat + k_mean
    kvp_kernel<<<dim3(8, BB * HH), 256>>>(p_kv, p_kvpart, p_kspart);
    kvred_kernel<<<BB * HH, 256>>>(p_kvpart, p_kspart, p_kvmat, p_kmean);
    // 10. attention out + lepe + act gate (fused) -> xab bf16
    attn_kernel<<<dim3(LL / 64, HH, BB), 256>>>(p_q, p_kvmat, p_kmean, p_kv,
                                                p_act, lepe_w, lepe_b, p_xab);
    // 11. x2 = shortcut + xab @ out_w + b
    tc_gemm<0, true, false><<<G4, 256, SM_SZ>>>(tmXab, tmWout, out_b, nullptr, p_x, p_x2, nullptr, CC, CC);
    // 12+13. x3 = x2 + cpe2(x2); ln = LN2(x3) (bf16)
    cpe_ln_kernel<<<TOK, 128>>>(p_x2, cpe2_w, cpe2_b, n2_g, n2_b, p_x3, p_ln);
    // 14. h1 = bf16(gelu(ln @ fc1_w + b))
    tc_gemm<3, false, true><<<G16, 256, SM_SZ>>>(tmLn, tmWfc1, fc1_b, nullptr, nullptr, (float*)p_h1, nullptr, MH, CC);
    // 15. out = x3 + h1 @ fc2_w + b (fp32)
    tc_gemm<0, true, false><<<G4, 256, SM_SZ>>>(tmH1, tmWfc2, fc2_b, nullptr, p_x3, outp, nullptr, CC, MH);
}

// round 15
// speedup vs baseline: 1.0504x; 1.0504x over previous
#include <cuda_runtime.h>
#include <cuda.h>
#include <cuda_bf16.h>
#include <math.h>
#include <stdint.h>

#define BB 8
#define LL 2048
#define CC 512
#define HH 8
#define HDIM 64
#define MH 2048
#define TOK (BB*LL)

#if defined(__CUDA_ARCH__) && (defined(__CUDA_ARCH_FEAT_SM103_ALL) || defined(__CUDA_ARCH_SPECIFIC__))
#define HAS_TCGEN05 1
#else
#define HAS_TCGEN05 0
#endif

// ---------------- scratch ---------------------------------------------------
__device__ __align__(1024) float g_x   [TOK*CC];
__device__ __align__(1024) float g_x2  [TOK*CC];
__device__ __align__(1024) float g_x3  [TOK*CC];
__device__ __align__(1024) __nv_bfloat16 g_ln  [TOK*CC];
__device__ __align__(1024) __nv_bfloat16 g_act [TOK*CC];
__device__ __align__(1024) __nv_bfloat16 g_xp  [TOK*CC];
__device__ __align__(1024) __nv_bfloat16 g_xp2 [TOK*CC];
__device__ __align__(1024) __nv_bfloat16 g_kv  [TOK*2*CC];
__device__ __align__(1024) __nv_bfloat16 g_q   [TOK*CC];
__device__ __align__(1024) __nv_bfloat16 g_xqr [TOK*CC];
__device__ __align__(1024) __nv_bfloat16 g_xab [TOK*CC];
__device__ __align__(1024) __nv_bfloat16 g_h1  [TOK*MH];
__device__ __align__(1024) __nv_bfloat16 g_wT  [3670016];
__device__ float g_kvpart[64*8*HDIM*HDIM];
__device__ float g_kspart[64*8*HDIM];
__device__ float g_kmean[BB*CC];
__device__ float g_kvmat[BB*HH*HDIM*HDIM];

#define WT_ACT 0
#define WT_IN  262144
#define WT_Q   524288
#define WT_KV  786432
#define WT_OUT 1310720
#define WT_FC1 1572864
#define WT_FC2 2621440

// ---------------- PTX helpers ---------------------------------------------
__device__ __forceinline__ uint32_t smem_u32(const void* p) {
    uint32_t a;
    asm("{ .reg .u64 t; cvta.to.shared.u64 t, %1; cvt.u32.u64 %0, t; }" : "=r"(a) : "l"(p));
    return a;
}
#define PKBF(res, lo, hi) \
    asm("cvt.rn.bf16x2.f32 %0, %1, %2;" : "=r"(res) : "f"(hi), "f"(lo))

__device__ __forceinline__ float4 ld_bf4(const __nv_bfloat16* p) {
    const uint2 u = *(const uint2*)p;
    const __nv_bfloat162 lo = *reinterpret_cast<const __nv_bfloat162*>(&u.x);
    const __nv_bfloat162 hi = *reinterpret_cast<const __nv_bfloat162*>(&u.y);
    const float2 f0 = __bfloat1622float2(lo);
    const float2 f1 = __bfloat1622float2(hi);
    return make_float4(f0.x, f0.y, f1.x, f1.y);
}

#define MBAR_INIT(a, c) \
    asm volatile("mbarrier.init.shared.b64 [%0], %1;" :: "r"(a), "r"(c) : "memory")
#define MBAR_EXPECT_TX(a, b) \
    asm volatile("mbarrier.arrive.expect_tx.shared.b64 _, [%0], %1;" :: "r"(a), "r"(b) : "memory")
#define MBAR_WAIT(a, ph) do { \
    asm volatile("{\n\t.reg .pred P;\n\tWL_%=:\n\t" \
        "mbarrier.try_wait.parity.acquire.cta.shared::cta.b64 P, [%0], %1, 0x989680;\n\t" \
        "@P bra.uni WD_%=;\n\tbra.uni WL_%=;\n\tWD_%=:\n\t}" \
        :: "r"(a), "r"(ph) : "memory"); } while (0)
#define TMA_LOAD2D(sm, mp, cx, cy, mb) \
    asm volatile("cp.async.bulk.tensor.2d.shared::cta.global.tile.mbarrier::complete_tx::bytes " \
        "[%0], [%1, {%2, %3}], [%4];" \
        :: "r"(sm), "l"(mp), "r"(cx), "r"(cy), "r"(mb) : "memory")

__device__ __forceinline__ void mma16n8k16bf(float* c, const uint32_t* a, const uint32_t* b) {
    asm volatile("mma.sync.aligned.m16n8k16.row.col.f32.bf16.bf16.f32 "
        "{%0,%1,%2,%3}, {%4,%5,%6,%7}, {%8,%9}, {%0,%1,%2,%3};"
        : "+f"(c[0]), "+f"(c[1]), "+f"(c[2]), "+f"(c[3])
        : "r"(a[0]), "r"(a[1]), "r"(a[2]), "r"(a[3]), "r"(b[0]), "r"(b[1]));
}

#if HAS_TCGEN05
#define TC_ALLOC(sm, n) \
    asm volatile("tcgen05.alloc.cta_group::1.sync.aligned.shared::cta.b32 [%0], %1;" :: "r"(sm), "r"(n) : "memory")
#define TC_DEALLOC(t, n) \
    asm volatile("tcgen05.dealloc.cta_group::1.sync.aligned.b32 %0, %1;" :: "r"(t), "r"(n))
#define TC_RELINQ() \
    asm volatile("tcgen05.relinquish_alloc_permit.cta_group::1.sync.aligned;")
#define TC_COMMIT(mb) \
    asm volatile("tcgen05.commit.cta_group::1.mbarrier::arrive::one.shared::cluster.b64 [%0];" :: "r"(mb) : "memory")
#define TC_FENCE_AFTER()  asm volatile("tcgen05.fence::after_thread_sync;" ::: "memory")
#define TC_FENCE_BEFORE() asm volatile("tcgen05.fence::before_thread_sync;" ::: "memory")
#define TC_WAIT_LD()      asm volatile("tcgen05.wait::ld.sync.aligned;" ::: "memory")
#define TC_LD32(r, ta) \
    asm volatile("tcgen05.ld.sync.aligned.32x32b.x32.b32 " \
        "{%0,%1,%2,%3,%4,%5,%6,%7,%8,%9,%10,%11,%12,%13,%14,%15," \
        "%16,%17,%18,%19,%20,%21,%22,%23,%24,%25,%26,%27,%28,%29,%30,%31}, [%32];" \
        : "=r"((r)[0]),"=r"((r)[1]),"=r"((r)[2]),"=r"((r)[3]),"=r"((r)[4]),"=r"((r)[5]), \
          "=r"((r)[6]),"=r"((r)[7]),"=r"((r)[8]),"=r"((r)[9]),"=r"((r)[10]),"=r"((r)[11]), \
          "=r"((r)[12]),"=r"((r)[13]),"=r"((r)[14]),"=r"((r)[15]),"=r"((r)[16]),"=r"((r)[17]), \
          "=r"((r)[18]),"=r"((r)[19]),"=r"((r)[20]),"=r"((r)[21]),"=r"((r)[22]),"=r"((r)[23]), \
          "=r"((r)[24]),"=r"((r)[25]),"=r"((r)[26]),"=r"((r)[27]),"=r"((r)[28]),"=r"((r)[29]), \
          "=r"((r)[30]),"=r"((r)[31]) : "r"(ta))

__device__ __forceinline__ void mma_bf16_ss(uint32_t d, uint64_t ad, uint64_t bd,
                                            uint32_t idesc, uint32_t en) {
    asm volatile("{\n\t.reg .pred p;\n\tsetp.ne.u32 p, %5, 0;\n\t"
        "tcgen05.mma.cta_group::1.kind::f16 [%0], %1, %2, %3, {%4, %4, %4, %4}, p;\n\t}"
        :: "r"(d), "l"(ad), "l"(bd), "r"(idesc), "r"(0u), "r"(en) : "memory");
}
#endif

#define DESC_SW128 ((2ull << 61) | (1ull << 46) | (64ull << 32) | (1ull << 16))
#define MK_DESC(a)  (DESC_SW128 | (((uint64_t)((a) >> 4)) & 0x3FFF))
// idesc kind::f16 bf16: N=256 -> 32<<17, M=128 -> 8<<24
#define IDESC_BF16 ((1u << 4) | (1u << 7) | (1u << 10) | (32u << 17) | (8u << 24))

// EPI: 0 none, 2 elu+1, 3 gelu, 4 elu+1 on cols<N/2, 5 merged silu/none
template<int EPI>
__device__ __forceinline__ float epi_fn(float v, int gcol, int N, bool silu5) {
    if (EPI == 2) v = (v > 0.f) ? v + 1.f : __expf(v);
    else if (EPI == 3) v = 0.5f * v * (1.f + erff(v * 0.70710678118654752f));
    else if (EPI == 4) { if (gcol < (N >> 1)) v = (v > 0.f) ? v + 1.f : __expf(v); }
    else if (EPI == 5) { if (silu5) v = v / (1.f + __expf(-v)); }
    return v;
}

__device__ __forceinline__ uint32_t swzb(int r, int c) {
    const uint32_t off = (uint32_t)(r * 128 + c * 2);
    return off ^ ((off >> 3) & 0x70);
}

// ---- tensor-core GEMM, 128x256 tile, bf16, 2-stage ring, 2 CTAs/SM --------
#define TN 256
#define SM_TMEMP 0
#define SM_FULLB(i) (8 + 8*(i))
#define SM_DONEB(i) (24 + 8*(i))
#define SM_FINAL 40
#define SM_STG 1024
#define STG_SZ (16384 + 32768)
#define SM_SZ (1024 + 2*STG_SZ)

// OBF: output stored as bf16 (out ptr reinterpreted)
template<int EPI, bool RES, bool OBF>
__global__ __launch_bounds__(256, 2) void tc_gemm(
    const __grid_constant__ CUtensorMap tmA,
    const __grid_constant__ CUtensorMap tmB,
    const float* __restrict__ bias, const float* __restrict__ bias2,
    const float* __restrict__ res,
    float* __restrict__ out, float* __restrict__ out2, int N, int K)
{
    extern __shared__ char smem[];
    const uint32_t sb = smem_u32(smem);
    const int tid = threadIdx.x;
    const int wid = tid >> 5, lane = tid & 31;
    const int bx = blockIdx.x, by = blockIdx.y;
    const int nK = K >> 6;

    float* op = out;
    const float* bp = bias;
    int colb = bx * TN;
    bool silu5 = false;
    if (EPI == 5) {
        const int hx = gridDim.x >> 1;
        if (bx < hx) silu5 = true;
        else { op = out2; bp = bias2; colb = (bx - hx) * TN; }
    }

#if HAS_TCGEN05
    if (tid == 0) {
#pragma unroll
        for (int i = 0; i < 2; i++) { MBAR_INIT(sb + SM_FULLB(i), 1); MBAR_INIT(sb + SM_DONEB(i), 1); }
        MBAR_INIT(sb + SM_FINAL, 1);
    }
    if (wid == 0) { TC_ALLOC(sb + SM_TMEMP, 256); TC_RELINQ(); }
    __syncthreads();
    uint32_t tmem;
    asm volatile("ld.shared.b32 %0, [%1];" : "=r"(tmem) : "r"(sb + SM_TMEMP));

    if (tid == 0) {
        int phd[2] = { 0, 0 };
        for (int kt = 0; kt < nK; kt++) {
            const int buf = kt & 1;
            if (kt >= 2) { MBAR_WAIT(sb + SM_DONEB(buf), phd[buf]); phd[buf] ^= 1; }
            MBAR_EXPECT_TX(sb + SM_FULLB(buf), 49152u);
            const uint32_t st = sb + SM_STG + buf * STG_SZ;
            TMA_LOAD2D(st,         &tmA, kt * 64, by * 128, sb + SM_FULLB(buf));
            TMA_LOAD2D(st + 16384, &tmB, kt * 64, bx * TN, sb + SM_FULLB(buf));
        }
    } else if (tid == 32) {
        int phf[2] = { 0, 0 };
        for (int kt = 0; kt < nK; kt++) {
            const int buf = kt & 1;
            MBAR_WAIT(sb + SM_FULLB(buf), phf[buf]); phf[buf] ^= 1;
            const uint32_t st = sb + SM_STG + buf * STG_SZ;
            const uint64_t ad = MK_DESC(st);
            const uint64_t bd = MK_DESC(st + 16384);
#pragma unroll
            for (int s = 0; s < 4; s++)
                mma_bf16_ss(tmem, ad + s * 2, bd + s * 2, IDESC_BF16,
                            (kt > 0 || s > 0) ? 1u : 0u);
            TC_COMMIT(sb + SM_DONEB(buf));
        }
        TC_COMMIT(sb + SM_FINAL);
    }

    MBAR_WAIT(sb + SM_FINAL, 0);
    TC_FENCE_AFTER();

    // epilogue: 8 warps; warp w: rows (w&3)*32, col chunk pairs (w>>2)*4 + 2*hp
    const int row = by * 128 + (wid & 3) * 32 + lane;
#pragma unroll
    for (int hp = 0; hp < 2; hp++) {
        const int cc0 = (wid >> 2) * 4 + hp * 2;
        uint32_t r0[32], r1[32];
        TC_LD32(r0, tmem + cc0 * 32);
        TC_LD32(r1, tmem + (cc0 + 1) * 32);
        TC_WAIT_LD();
#pragma unroll
        for (int half = 0; half < 2; half++) {
            const uint32_t* r = half ? r1 : r0;
            const int col = colb + (cc0 + half) * 32;
            const size_t o = (size_t)row * N + col;
            float vbuf[32];
#pragma unroll
            for (int j = 0; j < 32; j++) {
                float v = __uint_as_float(r[j]) + bp[col + j];
                v = epi_fn<EPI>(v, col + j, N, silu5);
                if (RES) v += res[o + j];
                vbuf[j] = v;
            }
            if (OBF) {
                uint32_t pk[16];
#pragma unroll
                for (int j = 0; j < 16; j++) PKBF(pk[j], vbuf[2 * j], vbuf[2 * j + 1]);
                uint4* dst = (uint4*)((__nv_bfloat16*)op + o);
#pragma unroll
                for (int j = 0; j < 4; j++)
                    dst[j] = make_uint4(pk[4 * j], pk[4 * j + 1], pk[4 * j + 2], pk[4 * j + 3]);
            } else {
#pragma unroll
                for (int j = 0; j < 8; j++)
                    *(float4*)(op + o + j * 4) = *(float4*)(&vbuf[j * 4]);
            }
        }
    }
    TC_FENCE_BEFORE();
    __syncthreads();
    if (wid == 0) TC_DEALLOC(tmem, 256);

#else
    // fallback: mma.sync bf16 m16n8k16, single stage, two 128-col half passes
    if (tid == 0) MBAR_INIT(sb + SM_FULLB(0), 1);
    __syncthreads();

    const char* As = smem + SM_STG;
    const char* Bs = smem + SM_STG + 16384;
    const int wm = wid >> 2;
    const int wn = wid & 3;
    int ph = 0;

    for (int nh = 0; nh < 2; nh++) {
        float c[4][4][4];
#pragma unroll
        for (int i = 0; i < 4; i++)
#pragma unroll
            for (int j = 0; j < 4; j++)
#pragma unroll
                for (int q = 0; q < 4; q++) c[i][j][q] = 0.f;

        for (int kt = 0; kt < nK; kt++) {
            __syncthreads();
            if (tid == 0) {
                MBAR_EXPECT_TX(sb + SM_FULLB(0), 49152u);
                TMA_LOAD2D(sb + SM_STG,         &tmA, kt * 64, by * 128, sb + SM_FULLB(0));
                TMA_LOAD2D(sb + SM_STG + 16384, &tmB, kt * 64, bx * TN, sb + SM_FULLB(0));
            }
            MBAR_WAIT(sb + SM_FULLB(0), ph); ph ^= 1;

#pragma unroll
            for (int s = 0; s < 4; s++) {
                const int k0 = s * 16;
                uint32_t af[4][4];
#pragma unroll
                for (int i = 0; i < 4; i++) {
                    const int r0 = wm * 64 + i * 16 + (lane >> 2);
                    af[i][0] = *(const uint32_t*)(As + swzb(r0,     k0 + 2 * (lane & 3)));
                    af[i][1] = *(const uint32_t*)(As + swzb(r0 + 8, k0 + 2 * (lane & 3)));
                    af[i][2] = *(const uint32_t*)(As + swzb(r0,     k0 + 8 + 2 * (lane & 3)));
                    af[i][3] = *(const uint32_t*)(As + swzb(r0 + 8, k0 + 8 + 2 * (lane & 3)));
                }
                uint32_t bf[4][2];
#pragma unroll
                for (int j = 0; j < 4; j++) {
                    const int n = nh * 128 + wn * 32 + j * 8 + (lane >> 2);
                    bf[j][0] = *(const uint32_t*)(Bs + swzb(n, k0 + 2 * (lane & 3)));
                    bf[j][1] = *(const uint32_t*)(Bs + swzb(n, k0 + 8 + 2 * (lane & 3)));
                }
#pragma unroll
                for (int i = 0; i < 4; i++)
#pragma unroll
                    for (int j = 0; j < 4; j++)
                        mma16n8k16bf(c[i][j], af[i], bf[j]);
            }
        }

#pragma unroll
        for (int i = 0; i < 4; i++) {
            const int r0 = by * 128 + wm * 64 + i * 16 + (lane >> 2);
#pragma unroll
            for (int j = 0; j < 4; j++) {
                const int cn = colb + nh * 128 + wn * 32 + j * 8 + 2 * (lane & 3);
#pragma unroll
                for (int q = 0; q < 4; q++) {
                    const int rr = r0 + (q >> 1) * 8;
                    const int gc = cn + (q & 1);
                    const size_t o = (size_t)rr * N + gc;
                    float v = c[i][j][q] + bp[gc];
                    v = epi_fn<EPI>(v, gc, N, silu5);
                    if (RES) v += res[o];
                    if (OBF) ((__nv_bfloat16*)op)[o] = __float2bfloat16(v);
                    else op[o] = v;
                }
            }
        }
    }
#endif
}

// ---------------- fused prep: 7 weight transposes (->bf16) + x_q round -----
#define ROUND_BLKS 8192
struct PrepTab {
    const float* src[7];
    int dst[7];
    int K[7];
    int N[7];
    int boff[8];
};

__global__ void prep_kernel(const __grid_constant__ PrepTab tab,
                            const float* __restrict__ xq,
                            __nv_bfloat16* __restrict__ xqr,
                            __nv_bfloat16* __restrict__ wT)
{
    const int bid = blockIdx.x;
    const int tid = threadIdx.x;
    if (bid < ROUND_BLKS) {
        const int idx = bid * 1024 + tid * 4;
        const float4 v = *(const float4*)(xq + idx);
        uint32_t p0, p1;
        PKBF(p0, v.x, v.y);
        PKBF(p1, v.z, v.w);
        *(uint2*)(xqr + idx) = make_uint2(p0, p1);
        return;
    }
    const int rb = bid - ROUND_BLKS;
    int i = 0;
#pragma unroll
    for (int s = 1; s < 7; s++) if (rb >= tab.boff[s]) i = s;
    const int local = rb - tab.boff[i];
    const int K = tab.K[i], N = tab.N[i];
    const int nbx = N >> 5;
    const int n0 = (local % nbx) * 32;
    const int k0 = (local / nbx) * 32;
    const float* in = tab.src[i];
    __nv_bfloat16* out = wT + tab.dst[i];

    __shared__ float t[32][33];
    const int tx = tid & 31, ty = tid >> 5;
#pragma unroll
    for (int it = 0; it < 4; it++)
        t[ty + it * 8][tx] = in[(size_t)(k0 + ty + it * 8) * N + n0 + tx];
    __syncthreads();
#pragma unroll
    for (int it = 0; it < 4; it++)
        out[(size_t)(n0 + ty + it * 8) * K + k0 + tx] = __float2bfloat16(t[tx][ty + it * 8]);
}

// --------- fused cpe conv + LayerNorm (LN out -> bf16) ---------------------
__global__ void cpe_ln_kernel(const float* __restrict__ x,
                              const float* __restrict__ w,
                              const float* __restrict__ cb,
                              const float* __restrict__ g,
                              const float* __restrict__ b,
                              float* __restrict__ xout,
                              __nv_bfloat16* __restrict__ lnout)
{
    const int row = blockIdx.x;
    const int l = row & (LL - 1);
    const int tid = threadIdx.x;
    const int c0 = tid * 4;

    const float4 vm = ((const float4*)(x + (size_t)row * CC))[tid];
    float4 vp = make_float4(0.f, 0.f, 0.f, 0.f);
    float4 vn = make_float4(0.f, 0.f, 0.f, 0.f);
    if (l > 0)      vp = ((const float4*)(x + (size_t)(row - 1) * CC))[tid];
    if (l < LL - 1) vn = ((const float4*)(x + (size_t)(row + 1) * CC))[tid];

    const float xm[4] = { vm.x, vm.y, vm.z, vm.w };
    const float xpv[4] = { vp.x, vp.y, vp.z, vp.w };
    const float xnv[4] = { vn.x, vn.y, vn.z, vn.w };
    float o[4];
#pragma unroll
    for (int j = 0; j < 4; j++) {
        const int c = c0 + j;
        float s = cb[c] + w[c * 3 + 0] * xpv[j] + w[c * 3 + 1] * xm[j]
                        + w[c * 3 + 2] * xnv[j];
        o[j] = xm[j] + s;
    }
    *(float4*)(xout + (size_t)row * CC + c0) = *(float4*)o;

    float s  = o[0] + o[1] + o[2] + o[3];
    float sq = o[0]*o[0] + o[1]*o[1] + o[2]*o[2] + o[3]*o[3];
#pragma unroll
    for (int of = 16; of; of >>= 1) {
        s  += __shfl_xor_sync(0xffffffffu, s,  of);
        sq += __shfl_xor_sync(0xffffffffu, sq, of);
    }
    __shared__ float ssum[4], ssq[4];
    const int wd = tid >> 5;
    if ((tid & 31) == 0) { ssum[wd] = s; ssq[wd] = sq; }
    __syncthreads();
    const float tot  = ssum[0] + ssum[1] + ssum[2] + ssum[3];
    const float totq = ssq[0]  + ssq[1]  + ssq[2]  + ssq[3];
    const float mu  = tot * (1.f / CC);
    const float var = totq * (1.f / CC) - mu * mu;
    const float rs  = rsqrtf(var + 1e-5f);
    float ov[4];
#pragma unroll
    for (int j = 0; j < 4; j++)
        ov[j] = (o[j] - mu) * rs * g[c0 + j] + b[c0 + j];
    uint32_t p0, p1;
    PKBF(p0, ov[0], ov[1]);
    PKBF(p1, ov[2], ov[3]);
    *(uint2*)(lnout + (size_t)row * CC + c0) = make_uint2(p0, p1);
}

// --------- dwc (reshaped view, bf16 in), silu -> bf16, x4 ------------------
__global__ void dwc_kernel(const __nv_bfloat16* __restrict__ in,
                           const float* __restrict__ w,
                           const float* __restrict__ bias,
                           __nv_bfloat16* __restrict__ out)
{
    const int t = blockIdx.x * blockDim.x + threadIdx.x;
    const int idx = t * 4;
    const int f = idx & (LL * CC - 1);
    const int r = f >> 11;
    const int j0 = f & (LL - 1);
    const float4 v = ld_bf4(in + idx);
    const float w0 = w[r * 3], w1 = w[r * 3 + 1], w2 = w[r * 3 + 2], bb = bias[r];
    float a[6];
    a[0] = (j0 > 0) ? __bfloat162float(in[idx - 1]) : 0.f;
    a[1] = v.x; a[2] = v.y; a[3] = v.z; a[4] = v.w;
    a[5] = (j0 + 4 < LL) ? __bfloat162float(in[idx + 4]) : 0.f;
    float o[4];
#pragma unroll
    for (int jj = 0; jj < 4; jj++) {
        const int j = j0 + jj;
        float s = bb + w1 * a[jj + 1];
        if (j > 0)      s += w0 * a[jj];
        if (j < LL - 1) s += w2 * a[jj + 2];
        o[jj] = s / (1.f + __expf(-s));
    }
    uint32_t p0, p1;
    PKBF(p0, o[0], o[1]);
    PKBF(p1, o[2], o[3]);
    *(uint2*)(out + idx) = make_uint2(p0, p1);
}

// --------- kv partial: K^T V (64x64) + k colsum (kv bf16) -------------------
__global__ __launch_bounds__(256) void kvp_kernel(const __nv_bfloat16* __restrict__ kv,
                                                  float* __restrict__ kvpart,
                                                  float* __restrict__ kspart)
{
    const int chunk = blockIdx.x;
    const int bh = blockIdx.y;
    const int b = bh >> 3, h = bh & 7;
    __shared__ float ks[64][64];
    __shared__ float vs[64][64];
    const int tid = threadIdx.x;
    const int d0 = (tid >> 4) << 2, e0 = (tid & 15) << 2;
    float acc[4][4];
#pragma unroll
    for (int i = 0; i < 4; i++)
#pragma unroll
        for (int j = 0; j < 4; j++) acc[i][j] = 0.f;
    float ksum = 0.f;

    const __nv_bfloat16* kb = kv + (size_t)b * LL * (2 * CC) + h * HDIM;
    const __nv_bfloat16* vb = kb + CC;
    const int row0 = chunk * 256;
    for (int n0 = row0; n0 < row0 + 256; n0 += 64) {
#pragma unroll
        for (int i = 0; i < 4; i++) {
            int v = tid + i * 256;
            int r = v >> 4; int c = (v & 15) << 2;
            *(float4*)(&ks[r][c]) = ld_bf4(kb + (size_t)(n0 + r) * (2 * CC) + c);
            *(float4*)(&vs[r][c]) = ld_bf4(vb + (size_t)(n0 + r) * (2 * CC) + c);
        }
        __syncthreads();
        if (tid < 64) {
            float s = 0.f;
#pragma unroll 16
            for (int n = 0; n < 64; n++) s += ks[n][tid];
            ksum += s;
        }
#pragma unroll 8
        for (int n = 0; n < 64; n++) {
            float a[4], bb[4];
            *(float4*)a  = *(float4*)(&ks[n][d0]);
            *(float4*)bb = *(float4*)(&vs[n][e0]);
#pragma unroll
            for (int i = 0; i < 4; i++)
#pragma unroll
                for (int j = 0; j < 4; j++)
                    acc[i][j] = fmaf(a[i], bb[j], acc[i][j]);
        }
        __syncthreads();
    }
    float* o = kvpart + ((size_t)bh * 8 + chunk) * (HDIM * HDIM);
#pragma unroll
    for (int i = 0; i < 4; i++)
#pragma unroll
        for (int j = 0; j < 4; j++)
            o[(d0 + i) * HDIM + e0 + j] = acc[i][j];
    if (tid < 64) kspart[((size_t)bh * 8 + chunk) * HDIM + tid] = ksum;
}

__global__ void kvred_kernel(const float* __restrict__ kvpart,
                             const float* __restrict__ kspart,
                             float* __restrict__ kvmat,
                             float* __restrict__ kmean)
{
    const int bh = blockIdx.x;
    const int tid = threadIdx.x;
#pragma unroll
    for (int i = 0; i < 16; i++) {
        const int e = i * 256 + tid;
        float s = 0.f;
#pragma unroll
        for (int c = 0; c < 8; c++)
            s += kvpart[((size_t)bh * 8 + c) * (HDIM * HDIM) + e];
        kvmat[(size_t)bh * (HDIM * HDIM) + e] = s * (1.f / LL);
    }
    if (tid < 64) {
        float s = 0.f;
#pragma unroll
        for (int c = 0; c < 8; c++)
            s += kspart[((size_t)bh * 8 + c) * HDIM + tid];
        kmean[(size_t)(bh >> 3) * CC + (bh & 7) * HDIM + tid] = s;
    }
}

// --------- attention out, FUSED with lepe conv + act gate -> xab bf16 ------
__global__ __launch_bounds__(256) void attn_kernel(
    const __nv_bfloat16* __restrict__ q,
    const float* __restrict__ kvmat,
    const float* __restrict__ kmean,
    const __nv_bfloat16* __restrict__ kv,
    const __nv_bfloat16* __restrict__ act,
    const float* __restrict__ lw,
    const float* __restrict__ lb,
    __nv_bfloat16* __restrict__ xab)
{
    const int n0 = blockIdx.x * 64;
    const int h = blockIdx.y, b = blockIdx.z;
    __shared__ float kvm[64][64];
    __shared__ float qT[64][65];
    __shared__ float km[64];
    __shared__ float zs[64];
    const int tid = threadIdx.x;

    const float* kvb = kvmat + ((size_t)(b * HH + h)) * (HDIM * HDIM);
#pragma unroll
    for (int i = 0; i < 4; i++) {
        int v = tid + i * 256;
        int r = v >> 4; int c = (v & 15) << 2;
        *(float4*)(&kvm[r][c]) = *(const float4*)(kvb + (size_t)r * 64 + c);
    }
    const __nv_bfloat16* qb = q + (size_t)b * LL * CC + (size_t)n0 * CC + h * HDIM;
#pragma unroll
    for (int i = 0; i < 4; i++) {
        int v = tid + i * 256;
        int t = v >> 4; int c = (v & 15) << 2;
        float4 q4 = ld_bf4(qb + (size_t)t * CC + c);
        qT[c + 0][t] = q4.x; qT[c + 1][t] = q4.y;
        qT[c + 2][t] = q4.z; qT[c + 3][t] = q4.w;
    }
    if (tid < 64) km[tid] = kmean[(size_t)b * CC + h * HDIM + tid] * (1.f / LL);
    __syncthreads();
    if (tid < 64) {
        float dot = 0.f;
#pragma unroll 16
        for (int d = 0; d < 64; d++) dot += qT[d][tid] * km[d];
        zs[tid] = 1.f / (dot + 1e-6f);
    }
    __syncthreads();

    const int t0 = (tid >> 4) << 2, e0 = (tid & 15) << 2;
    float acc[4][4];
#pragma unroll
    for (int i = 0; i < 4; i++)
#pragma unroll
        for (int j = 0; j < 4; j++) acc[i][j] = 0.f;
#pragma unroll 8
    for (int d = 0; d < 64; d++) {
        float a[4];
#pragma unroll
        for (int i = 0; i < 4; i++) a[i] = qT[d][t0 + i];
        float bb[4];
        *(float4*)bb = *(float4*)(&kvm[d][e0]);
#pragma unroll
        for (int i = 0; i < 4; i++)
#pragma unroll
            for (int j = 0; j < 4; j++)
                acc[i][j] = fmaf(a[i], bb[j], acc[i][j]);
    }

    const int gc0 = h * HDIM + e0;
    float w0[4], w1[4], w2[4], lb4[4];
#pragma unroll
    for (int j = 0; j < 4; j++) {
        w0[j]  = lw[(gc0 + j) * 3 + 0];
        w1[j]  = lw[(gc0 + j) * 3 + 1];
        w2[j]  = lw[(gc0 + j) * 3 + 2];
        lb4[j] = lb[gc0 + j];
    }
#pragma unroll
    for (int i = 0; i < 4; i++) {
        const int n = n0 + t0 + i;
        const size_t gn = (size_t)b * LL + n;
        const __nv_bfloat16* vr = kv + gn * (2 * CC) + CC + gc0;
        const float4 vmv = ld_bf4(vr);
        float4 vpv = make_float4(0.f, 0.f, 0.f, 0.f);
        float4 vnv = make_float4(0.f, 0.f, 0.f, 0.f);
        if (n > 0)      vpv = ld_bf4(vr - 2 * CC);
        if (n < LL - 1) vnv = ld_bf4(vr + 2 * CC);
        const float4 a4 = ld_bf4(act + gn * CC + gc0);
        const float z = zs[t0 + i];
        float o[4];
        o[0] = (acc[i][0] * z + lb4[0] + w0[0] * vpv.x + w1[0] * vmv.x + w2[0] * vnv.x) * a4.x;
        o[1] = (acc[i][1] * z + lb4[1] + w0[1] * vpv.y + w1[1] * vmv.y + w2[1] * vnv.y) * a4.y;
        o[2] = (acc[i][2] * z + lb4[2] + w0[2] * vpv.z + w1[2] * vmv.z + w2[2] * vnv.z) * a4.z;
        o[3] = (acc[i][3] * z + lb4[3] + w0[3] * vpv.w + w1[3] * vmv.w + w2[3] * vnv.w) * a4.w;
        uint32_t p0, p1;
        PKBF(p0, o[0], o[1]);
        PKBF(p1, o[2], o[3]);
        *(uint2*)(xab + gn * CC + gc0) = make_uint2(p0, p1);
    }
}

// ---------------------------------------------------------------------------
typedef CUresult (*PFN_encodeTiled)(CUtensorMap*, CUtensorMapDataType, cuuint32_t,
    void*, const cuuint64_t*, const cuuint64_t*, const cuuint32_t*, const cuuint32_t*,
    CUtensorMapInterleave, CUtensorMapSwizzle, CUtensorMapL2promotion, CUtensorMapFloatOOBfill);

static void mk2db(PFN_encodeTiled fn, CUtensorMap* m, const void* p,
                  unsigned long long inner, unsigned long long outer, unsigned boxY)
{
    cuuint64_t dims[2] = { inner, outer };
    cuuint64_t st[1]   = { inner * 2 };
    cuuint32_t box[2]  = { 64, boxY };
    cuuint32_t es[2]   = { 1, 1 };
    fn(m, CU_TENSOR_MAP_DATA_TYPE_BFLOAT16, 2, (void*)p, dims, st, box, es,
       CU_TENSOR_MAP_INTERLEAVE_NONE, CU_TENSOR_MAP_SWIZZLE_128B,
       CU_TENSOR_MAP_L2_PROMOTION_L2_128B, CU_TENSOR_MAP_FLOAT_OOB_FILL_NONE);
}

extern "C" void kernel_launch(void* const* d_in, const int* in_sizes, int n_in,
                              void* d_out, int out_size)
{
    const float* x_q    = (const float*)d_in[0];
    const float* x_kv   = (const float*)d_in[1];
    const float* cpe1_w = (const float*)d_in[2];
    const float* cpe1_b = (const float*)d_in[3];
    const float* n1_g   = (const float*)d_in[4];
    const float* n1_b   = (const float*)d_in[5];
    const float* in_w   = (const float*)d_in[6];
    const float* in_b   = (const float*)d_in[7];
    const float* act_w  = (const float*)d_in[8];
    const float* act_b  = (const float*)d_in[9];
    const float* dwc_w  = (const float*)d_in[10];
    const float* dwc_b  = (const float*)d_in[11];
    const float* q_w    = (const float*)d_in[12];
    const float* q_b    = (const float*)d_in[13];
    const float* kv_w   = (const float*)d_in[14];
    const float* kv_b   = (const float*)d_in[15];
    const float* lepe_w = (const float*)d_in[16];
    const float* lepe_b = (const float*)d_in[17];
    const float* out_w  = (const float*)d_in[18];
    const float* out_b  = (const float*)d_in[19];
    const float* cpe2_w = (const float*)d_in[20];
    const float* cpe2_b = (const float*)d_in[21];
    const float* n2_g   = (const float*)d_in[22];
    const float* n2_b   = (const float*)d_in[23];
    const float* fc1_w  = (const float*)d_in[24];
    const float* fc1_b  = (const float*)d_in[25];
    const float* fc2_w  = (const float*)d_in[26];
    const float* fc2_b  = (const float*)d_in[27];
    float* outp = (float*)d_out;

    float *p_x, *p_x2, *p_x3, *p_kvpart, *p_kspart, *p_kmean, *p_kvmat;
    __nv_bfloat16 *p_ln, *p_act, *p_xp, *p_xp2, *p_kv, *p_q, *p_xqr, *p_xab, *p_h1, *p_wT;
    cudaGetSymbolAddress((void**)&p_x,      g_x);
    cudaGetSymbolAddress((void**)&p_x2,     g_x2);
    cudaGetSymbolAddress((void**)&p_x3,     g_x3);
    cudaGetSymbolAddress((void**)&p_ln,     g_ln);
    cudaGetSymbolAddress((void**)&p_act,    g_act);
    cudaGetSymbolAddress((void**)&p_xp,     g_xp);
    cudaGetSymbolAddress((void**)&p_xp2,    g_xp2);
    cudaGetSymbolAddress((void**)&p_kv,     g_kv);
    cudaGetSymbolAddress((void**)&p_q,      g_q);
    cudaGetSymbolAddress((void**)&p_xqr,    g_xqr);
    cudaGetSymbolAddress((void**)&p_xab,    g_xab);
    cudaGetSymbolAddress((void**)&p_h1,     g_h1);
    cudaGetSymbolAddress((void**)&p_wT,     g_wT);
    cudaGetSymbolAddress((void**)&p_kvpart, g_kvpart);
    cudaGetSymbolAddress((void**)&p_kspart, g_kspart);
    cudaGetSymbolAddress((void**)&p_kmean,  g_kmean);
    cudaGetSymbolAddress((void**)&p_kvmat,  g_kvmat);

    PFN_encodeTiled enc = nullptr;
#if CUDART_VERSION >= 12050
    {
        cudaDriverEntryPointQueryResult qr;
        cudaGetDriverEntryPointByVersion("cuTensorMapEncodeTiled", (void**)&enc,
                                         12000, cudaEnableDefault, &qr);
    }
#else
    {
        cudaDriverEntryPointQueryResult qr;
        cudaGetDriverEntryPoint("cuTensorMapEncodeTiled", (void**)&enc,
                                cudaEnableDefault, &qr);
    }
#endif

    CUtensorMap tmLn, tmXqr, tmXp2, tmXab, tmH1;
    CUtensorMap tmWai, tmWq, tmWkv, tmWout, tmWfc1, tmWfc2;
    mk2db(enc, &tmLn,  p_ln,  CC, TOK, 128);
    mk2db(enc, &tmXqr, p_xqr, CC, TOK, 128);
    mk2db(enc, &tmXp2, p_xp2, CC, TOK, 128);
    mk2db(enc, &tmXab, p_xab, CC, TOK, 128);
    mk2db(enc, &tmH1,  p_h1,  MH, TOK, 128);
    mk2db(enc, &tmWai,  p_wT + WT_ACT, CC, 2 * CC, 256);
    mk2db(enc, &tmWq,   p_wT + WT_Q,   CC, CC,     256);
    mk2db(enc, &tmWkv,  p_wT + WT_KV,  CC, 2 * CC, 256);
    mk2db(enc, &tmWout, p_wT + WT_OUT, CC, CC,     256);
    mk2db(enc, &tmWfc1, p_wT + WT_FC1, CC, MH,     256);
    mk2db(enc, &tmWfc2, p_wT + WT_FC2, MH, CC,     256);

    cudaFuncSetAttribute(tc_gemm<5, false, true >, cudaFuncAttributeMaxDynamicSharedMemorySize, SM_SZ);
    cudaFuncSetAttribute(tc_gemm<4, false, true >, cudaFuncAttributeMaxDynamicSharedMemorySize, SM_SZ);
    cudaFuncSetAttribute(tc_gemm<2, false, true >, cudaFuncAttributeMaxDynamicSharedMemorySize, SM_SZ);
    cudaFuncSetAttribute(tc_gemm<0, true,  false>, cudaFuncAttributeMaxDynamicSharedMemorySize, SM_SZ);
    cudaFuncSetAttribute(tc_gemm<3, false, true >, cudaFuncAttributeMaxDynamicSharedMemorySize, SM_SZ);

    const int M = TOK;
    const int VEC_BLOCKS = (TOK * CC / 4) / 256;
    const dim3 G2(2, M / 128), G4(4, M / 128), G8(8, M / 128);

    // fused prep: 7 transposes (->bf16) + x_q round
    PrepTab tab;
    const float* srcs[7] = { act_w, in_w, q_w, kv_w, out_w, fc1_w, fc2_w };
    const int dsts[7] = { WT_ACT, WT_IN, WT_Q, WT_KV, WT_OUT, WT_FC1, WT_FC2 };
    const int Ks[7] = { CC, CC, CC, CC, CC, CC, MH };
    const int Ns[7] = { CC, CC, CC, 2*CC, CC, MH, CC };
    int off = 0;
    for (int i = 0; i < 7; i++) {
        tab.src[i] = srcs[i]; tab.dst[i] = dsts[i];
        tab.K[i] = Ks[i]; tab.N[i] = Ns[i];
        tab.boff[i] = off;
        off += (Ns[i] >> 5) * (Ks[i] >> 5);
    }
    tab.boff[7] = off;
    prep_kernel<<<ROUND_BLKS + off, 256>>>(tab, x_q, p_xqr, p_wT);

    // 1+2. x = x_kv + cpe1(x_kv); ln = LN1(x) (bf16)
    cpe_ln_kernel<<<TOK, 128>>>(x_kv, cpe1_w, cpe1_b, n1_g, n1_b, p_x, p_ln);
    // 3. q = bf16(elu(x_q @ q_w + b) + 1)
    tc_gemm<2, false, true><<<G2, 256, SM_SZ>>>(tmXqr, tmWq, q_b, nullptr, nullptr, (float*)p_q, nullptr, CC, CC);
    // 4+5. act = bf16(silu(ln@act_w+b)) ; xp = bf16(ln@in_w+b)
    tc_gemm<5, false, true><<<G4, 256, SM_SZ>>>(tmLn, tmWai, act_b, in_b, nullptr, (float*)p_act, (float*)p_xp, CC, CC);
    // 6. xp2 = bf16(silu(dwconv(reshape(xp))))
    dwc_kernel<<<VEC_BLOCKS, 256>>>(p_xp, dwc_w, dwc_b, p_xp2);
    // 7. kv = bf16(xp2 @ kv_w + b); elu+1 on k half
    tc_gemm<4, false, true><<<G4, 256, SM_SZ>>>(tmXp2, tmWkv, kv_b, nullptr, nullptr, (float*)p_kv, nullptr, 2 * CC, CC);
    // 8+9. kv_mat + k_mean
    kvp_kernel<<<dim3(8, BB * HH), 256>>>(p_kv, p_kvpart, p_kspart);
    kvred_kernel<<<BB * HH, 256>>>(p_kvpart, p_kspart, p_kvmat, p_kmean);
    // 10. attention out + lepe + act gate (fused) -> xab bf16
    attn_kernel<<<dim3(LL / 64, HH, BB), 256>>>(p_q, p_kvmat, p_kmean, p_kv,
                                                p_act, lepe_w, lepe_b, p_xab);
    // 11. x2 = shortcut + xab @ out_w + b
    tc_gemm<0, true, false><<<G2, 256, SM_SZ>>>(tmXab, tmWout, out_b, nullptr, p_x, p_x2, nullptr, CC, CC);
    // 12+13. x3 = x2 + cpe2(x2); ln = LN2(x3) (bf16)
    cpe_ln_kernel<<<TOK, 128>>>(p_x2, cpe2_w, cpe2_b, n2_g, n2_b, p_x3, p_ln);
    // 14. h1 = bf16(gelu(ln @ fc1_w + b))
    tc_gemm<3, false, true><<<G8, 256, SM_SZ>>>(tmLn, tmWfc1, fc1_b, nullptr, nullptr, (float*)p_h1, nullptr, MH, CC);
    // 15. out = x3 + h1 @ fc2_w + b (fp32)
    tc_gemm<0, true, false><<<G2, 256, SM_SZ>>>(tmH1, tmWfc2, fc2_b, nullptr, p_x3, outp, nullptr, CC, MH);
}

// round 16
// speedup vs baseline: 1.0679x; 1.0167x over previous
#include <cuda_runtime.h>
#include <cuda.h>
#include <cuda_bf16.h>
#include <math.h>
#include <stdint.h>

#define BB 8
#define LL 2048
#define CC 512
#define HH 8
#define HDIM 64
#define MH 2048
#define TOK (BB*LL)

#if defined(__CUDA_ARCH__) && (defined(__CUDA_ARCH_FEAT_SM103_ALL) || defined(__CUDA_ARCH_SPECIFIC__))
#define HAS_TCGEN05 1
#else
#define HAS_TCGEN05 0
#endif

// ---------------- scratch ---------------------------------------------------
__device__ __align__(1024) float g_x   [TOK*CC];
__device__ __align__(1024) float g_x2  [TOK*CC];
__device__ __align__(1024) float g_x3  [TOK*CC];
__device__ __align__(1024) __nv_bfloat16 g_ln  [TOK*CC];
__device__ __align__(1024) __nv_bfloat16 g_act [TOK*CC];
__device__ __align__(1024) __nv_bfloat16 g_xp  [TOK*CC];
__device__ __align__(1024) __nv_bfloat16 g_xp2 [TOK*CC];
__device__ __align__(1024) __nv_bfloat16 g_kv  [TOK*2*CC];
__device__ __align__(1024) __nv_bfloat16 g_q   [TOK*CC];
__device__ __align__(1024) __nv_bfloat16 g_xqr [TOK*CC];
__device__ __align__(1024) __nv_bfloat16 g_xab [TOK*CC];
__device__ __align__(1024) __nv_bfloat16 g_h1  [TOK*MH];
__device__ __align__(1024) __nv_bfloat16 g_wT  [3670016];
__device__ float g_kvpart[64*8*HDIM*HDIM];
__device__ float g_kspart[64*8*HDIM];
__device__ float g_kmean[BB*CC];
__device__ float g_kvmat[BB*HH*HDIM*HDIM];

#define WT_ACT 0
#define WT_IN  262144
#define WT_Q   524288
#define WT_KV  786432
#define WT_OUT 1310720
#define WT_FC1 1572864
#define WT_FC2 2621440

// ---------------- PTX helpers ---------------------------------------------
__device__ __forceinline__ uint32_t smem_u32(const void* p) {
    uint32_t a;
    asm("{ .reg .u64 t; cvta.to.shared.u64 t, %1; cvt.u32.u64 %0, t; }" : "=r"(a) : "l"(p));
    return a;
}
#define PKBF(res, lo, hi) \
    asm("cvt.rn.bf16x2.f32 %0, %1, %2;" : "=r"(res) : "f"(hi), "f"(lo))

// PDL: wait for prior grid's memory; allow dependents to launch early
#define GDC_WAIT()   asm volatile("griddepcontrol.wait;" ::: "memory")
#define GDC_LAUNCH() asm volatile("griddepcontrol.launch_dependents;" ::: "memory")

__device__ __forceinline__ float4 ld_bf4(const __nv_bfloat16* p) {
    const uint2 u = *(const uint2*)p;
    const __nv_bfloat162 lo = *reinterpret_cast<const __nv_bfloat162*>(&u.x);
    const __nv_bfloat162 hi = *reinterpret_cast<const __nv_bfloat162*>(&u.y);
    const float2 f0 = __bfloat1622float2(lo);
    const float2 f1 = __bfloat1622float2(hi);
    return make_float4(f0.x, f0.y, f1.x, f1.y);
}

#define MBAR_INIT(a, c) \
    asm volatile("mbarrier.init.shared.b64 [%0], %1;" :: "r"(a), "r"(c) : "memory")
#define MBAR_EXPECT_TX(a, b) \
    asm volatile("mbarrier.arrive.expect_tx.shared.b64 _, [%0], %1;" :: "r"(a), "r"(b) : "memory")
#define MBAR_WAIT(a, ph) do { \
    asm volatile("{\n\t.reg .pred P;\n\tWL_%=:\n\t" \
        "mbarrier.try_wait.parity.acquire.cta.shared::cta.b64 P, [%0], %1, 0x989680;\n\t" \
        "@P bra.uni WD_%=;\n\tbra.uni WL_%=;\n\tWD_%=:\n\t}" \
        :: "r"(a), "r"(ph) : "memory"); } while (0)
#define TMA_LOAD2D(sm, mp, cx, cy, mb) \
    asm volatile("cp.async.bulk.tensor.2d.shared::cta.global.tile.mbarrier::complete_tx::bytes " \
        "[%0], [%1, {%2, %3}], [%4];" \
        :: "r"(sm), "l"(mp), "r"(cx), "r"(cy), "r"(mb) : "memory")

__device__ __forceinline__ void mma16n8k16bf(float* c, const uint32_t* a, const uint32_t* b) {
    asm volatile("mma.sync.aligned.m16n8k16.row.col.f32.bf16.bf16.f32 "
        "{%0,%1,%2,%3}, {%4,%5,%6,%7}, {%8,%9}, {%0,%1,%2,%3};"
        : "+f"(c[0]), "+f"(c[1]), "+f"(c[2]), "+f"(c[3])
        : "r"(a[0]), "r"(a[1]), "r"(a[2]), "r"(a[3]), "r"(b[0]), "r"(b[1]));
}

#if HAS_TCGEN05
#define TC_ALLOC(sm, n) \
    asm volatile("tcgen05.alloc.cta_group::1.sync.aligned.shared::cta.b32 [%0], %1;" :: "r"(sm), "r"(n) : "memory")
#define TC_DEALLOC(t, n) \
    asm volatile("tcgen05.dealloc.cta_group::1.sync.aligned.b32 %0, %1;" :: "r"(t), "r"(n))
#define TC_RELINQ() \
    asm volatile("tcgen05.relinquish_alloc_permit.cta_group::1.sync.aligned;")
#define TC_COMMIT(mb) \
    asm volatile("tcgen05.commit.cta_group::1.mbarrier::arrive::one.shared::cluster.b64 [%0];" :: "r"(mb) : "memory")
#define TC_FENCE_AFTER()  asm volatile("tcgen05.fence::after_thread_sync;" ::: "memory")
#define TC_FENCE_BEFORE() asm volatile("tcgen05.fence::before_thread_sync;" ::: "memory")
#define TC_WAIT_LD()      asm volatile("tcgen05.wait::ld.sync.aligned;" ::: "memory")
#define TC_LD32(r, ta) \
    asm volatile("tcgen05.ld.sync.aligned.32x32b.x32.b32 " \
        "{%0,%1,%2,%3,%4,%5,%6,%7,%8,%9,%10,%11,%12,%13,%14,%15," \
        "%16,%17,%18,%19,%20,%21,%22,%23,%24,%25,%26,%27,%28,%29,%30,%31}, [%32];" \
        : "=r"((r)[0]),"=r"((r)[1]),"=r"((r)[2]),"=r"((r)[3]),"=r"((r)[4]),"=r"((r)[5]), \
          "=r"((r)[6]),"=r"((r)[7]),"=r"((r)[8]),"=r"((r)[9]),"=r"((r)[10]),"=r"((r)[11]), \
          "=r"((r)[12]),"=r"((r)[13]),"=r"((r)[14]),"=r"((r)[15]),"=r"((r)[16]),"=r"((r)[17]), \
          "=r"((r)[18]),"=r"((r)[19]),"=r"((r)[20]),"=r"((r)[21]),"=r"((r)[22]),"=r"((r)[23]), \
          "=r"((r)[24]),"=r"((r)[25]),"=r"((r)[26]),"=r"((r)[27]),"=r"((r)[28]),"=r"((r)[29]), \
          "=r"((r)[30]),"=r"((r)[31]) : "r"(ta))

__device__ __forceinline__ void mma_bf16_ss(uint32_t d, uint64_t ad, uint64_t bd,
                                            uint32_t idesc, uint32_t en) {
    asm volatile("{\n\t.reg .pred p;\n\tsetp.ne.u32 p, %5, 0;\n\t"
        "tcgen05.mma.cta_group::1.kind::f16 [%0], %1, %2, %3, {%4, %4, %4, %4}, p;\n\t}"
        :: "r"(d), "l"(ad), "l"(bd), "r"(idesc), "r"(0u), "r"(en) : "memory");
}
#endif

#define DESC_SW128 ((2ull << 61) | (1ull << 46) | (64ull << 32) | (1ull << 16))
#define MK_DESC(a)  (DESC_SW128 | (((uint64_t)((a) >> 4)) & 0x3FFF))
// idesc kind::f16 bf16: N=256 -> 32<<17, M=128 -> 8<<24
#define IDESC_BF16 ((1u << 4) | (1u << 7) | (1u << 10) | (32u << 17) | (8u << 24))

// EPI: 0 none, 2 elu+1, 3 gelu, 4 elu+1 on cols<N/2, 5 merged silu/none
template<int EPI>
__device__ __forceinline__ float epi_fn(float v, int gcol, int N, bool silu5) {
    if (EPI == 2) v = (v > 0.f) ? v + 1.f : __expf(v);
    else if (EPI == 3) v = 0.5f * v * (1.f + erff(v * 0.70710678118654752f));
    else if (EPI == 4) { if (gcol < (N >> 1)) v = (v > 0.f) ? v + 1.f : __expf(v); }
    else if (EPI == 5) { if (silu5) v = v / (1.f + __expf(-v)); }
    return v;
}

__device__ __forceinline__ uint32_t swzb(int r, int c) {
    const uint32_t off = (uint32_t)(r * 128 + c * 2);
    return off ^ ((off >> 3) & 0x70);
}

// ---- tensor-core GEMM, 128x256 tile, bf16, 2-stage ring, 2 CTAs/SM --------
#define TN 256
#define SM_TMEMP 0
#define SM_FULLB(i) (8 + 8*(i))
#define SM_DONEB(i) (24 + 8*(i))
#define SM_FINAL 40
#define SM_STG 1024
#define STG_SZ (16384 + 32768)
#define SM_SZ (1024 + 2*STG_SZ)

// OBF: output stored as bf16 (out ptr reinterpreted)
template<int EPI, bool RES, bool OBF>
__global__ __launch_bounds__(256, 2) void tc_gemm(
    const __grid_constant__ CUtensorMap tmA,
    const __grid_constant__ CUtensorMap tmB,
    const float* __restrict__ bias, const float* __restrict__ bias2,
    const float* __restrict__ res,
    float* __restrict__ out, float* __restrict__ out2, int N, int K)
{
    extern __shared__ char smem[];
    const uint32_t sb = smem_u32(smem);
    const int tid = threadIdx.x;
    const int wid = tid >> 5, lane = tid & 31;
    const int bx = blockIdx.x, by = blockIdx.y;
    const int nK = K >> 6;

    float* op = out;
    const float* bp = bias;
    int colb = bx * TN;
    bool silu5 = false;
    if (EPI == 5) {
        const int hx = gridDim.x >> 1;
        if (bx < hx) silu5 = true;
        else { op = out2; bp = bias2; colb = (bx - hx) * TN; }
    }

#if HAS_TCGEN05
    // input-independent prologue overlaps predecessor's tail (PDL)
    if (tid == 0) {
#pragma unroll
        for (int i = 0; i < 2; i++) { MBAR_INIT(sb + SM_FULLB(i), 1); MBAR_INIT(sb + SM_DONEB(i), 1); }
        MBAR_INIT(sb + SM_FINAL, 1);
    }
    if (wid == 0) { TC_ALLOC(sb + SM_TMEMP, 256); TC_RELINQ(); }
    __syncthreads();
    uint32_t tmem;
    asm volatile("ld.shared.b32 %0, [%1];" : "=r"(tmem) : "r"(sb + SM_TMEMP));

    GDC_WAIT();      // predecessor's global writes now visible
    GDC_LAUNCH();    // let successor pre-launch its prologue

    if (tid == 0) {
        int phd[2] = { 0, 0 };
        for (int kt = 0; kt < nK; kt++) {
            const int buf = kt & 1;
            if (kt >= 2) { MBAR_WAIT(sb + SM_DONEB(buf), phd[buf]); phd[buf] ^= 1; }
            MBAR_EXPECT_TX(sb + SM_FULLB(buf), 49152u);
            const uint32_t st = sb + SM_STG + buf * STG_SZ;
            TMA_LOAD2D(st,         &tmA, kt * 64, by * 128, sb + SM_FULLB(buf));
            TMA_LOAD2D(st + 16384, &tmB, kt * 64, bx * TN, sb + SM_FULLB(buf));
        }
    } else if (tid == 32) {
        int phf[2] = { 0, 0 };
        for (int kt = 0; kt < nK; kt++) {
            const int buf = kt & 1;
            MBAR_WAIT(sb + SM_FULLB(buf), phf[buf]); phf[buf] ^= 1;
            const uint32_t st = sb + SM_STG + buf * STG_SZ;
            const uint64_t ad = MK_DESC(st);
            const uint64_t bd = MK_DESC(st + 16384);
#pragma unroll
            for (int s = 0; s < 4; s++)
                mma_bf16_ss(tmem, ad + s * 2, bd + s * 2, IDESC_BF16,
                            (kt > 0 || s > 0) ? 1u : 0u);
            TC_COMMIT(sb + SM_DONEB(buf));
        }
        TC_COMMIT(sb + SM_FINAL);
    }

    MBAR_WAIT(sb + SM_FINAL, 0);
    TC_FENCE_AFTER();

    // epilogue: 8 warps; warp w: rows (w&3)*32, col chunks (w>>2)*4 + h
    const int row = by * 128 + (wid & 3) * 32 + lane;
#pragma unroll
    for (int h = 0; h < 4; h++) {
        const int cc = (wid >> 2) * 4 + h;
        uint32_t r[32];
        TC_LD32(r, tmem + cc * 32);
        TC_WAIT_LD();
        const int col = colb + cc * 32;
        const size_t o = (size_t)row * N + col;
        float vbuf[32];
#pragma unroll
        for (int j = 0; j < 32; j++) {
            float v = __uint_as_float(r[j]) + bp[col + j];
            v = epi_fn<EPI>(v, col + j, N, silu5);
            if (RES) v += res[o + j];
            vbuf[j] = v;
        }
        if (OBF) {
            uint32_t pk[16];
#pragma unroll
            for (int j = 0; j < 16; j++) PKBF(pk[j], vbuf[2 * j], vbuf[2 * j + 1]);
            uint4* dst = (uint4*)((__nv_bfloat16*)op + o);
#pragma unroll
            for (int j = 0; j < 4; j++)
                dst[j] = make_uint4(pk[4 * j], pk[4 * j + 1], pk[4 * j + 2], pk[4 * j + 3]);
        } else {
#pragma unroll
            for (int j = 0; j < 8; j++)
                *(float4*)(op + o + j * 4) = *(float4*)(&vbuf[j * 4]);
        }
    }
    TC_FENCE_BEFORE();
    __syncthreads();
    if (wid == 0) TC_DEALLOC(tmem, 256);

#else
    // fallback: mma.sync bf16 m16n8k16, single stage, two 128-col half passes
    if (tid == 0) MBAR_INIT(sb + SM_FULLB(0), 1);
    __syncthreads();
    GDC_WAIT();
    GDC_LAUNCH();

    const char* As = smem + SM_STG;
    const char* Bs = smem + SM_STG + 16384;
    const int wm = wid >> 2;
    const int wn = wid & 3;
    int ph = 0;

    for (int nh = 0; nh < 2; nh++) {
        float c[4][4][4];
#pragma unroll
        for (int i = 0; i < 4; i++)
#pragma unroll
            for (int j = 0; j < 4; j++)
#pragma unroll
                for (int q = 0; q < 4; q++) c[i][j][q] = 0.f;

        for (int kt = 0; kt < nK; kt++) {
            __syncthreads();
            if (tid == 0) {
                MBAR_EXPECT_TX(sb + SM_FULLB(0), 49152u);
                TMA_LOAD2D(sb + SM_STG,         &tmA, kt * 64, by * 128, sb + SM_FULLB(0));
                TMA_LOAD2D(sb + SM_STG + 16384, &tmB, kt * 64, bx * TN, sb + SM_FULLB(0));
            }
            MBAR_WAIT(sb + SM_FULLB(0), ph); ph ^= 1;

#pragma unroll
            for (int s = 0; s < 4; s++) {
                const int k0 = s * 16;
                uint32_t af[4][4];
#pragma unroll
                for (int i = 0; i < 4; i++) {
                    const int r0 = wm * 64 + i * 16 + (lane >> 2);
                    af[i][0] = *(const uint32_t*)(As + swzb(r0,     k0 + 2 * (lane & 3)));
                    af[i][1] = *(const uint32_t*)(As + swzb(r0 + 8, k0 + 2 * (lane & 3)));
                    af[i][2] = *(const uint32_t*)(As + swzb(r0,     k0 + 8 + 2 * (lane & 3)));
                    af[i][3] = *(const uint32_t*)(As + swzb(r0 + 8, k0 + 8 + 2 * (lane & 3)));
                }
                uint32_t bf[4][2];
#pragma unroll
                for (int j = 0; j < 4; j++) {
                    const int n = nh * 128 + wn * 32 + j * 8 + (lane >> 2);
                    bf[j][0] = *(const uint32_t*)(Bs + swzb(n, k0 + 2 * (lane & 3)));
                    bf[j][1] = *(const uint32_t*)(Bs + swzb(n, k0 + 8 + 2 * (lane & 3)));
                }
#pragma unroll
                for (int i = 0; i < 4; i++)
#pragma unroll
                    for (int j = 0; j < 4; j++)
                        mma16n8k16bf(c[i][j], af[i], bf[j]);
            }
        }

#pragma unroll
        for (int i = 0; i < 4; i++) {
            const int r0 = by * 128 + wm * 64 + i * 16 + (lane >> 2);
#pragma unroll
            for (int j = 0; j < 4; j++) {
                const int cn = colb + nh * 128 + wn * 32 + j * 8 + 2 * (lane & 3);
#pragma unroll
                for (int q = 0; q < 4; q++) {
                    const int rr = r0 + (q >> 1) * 8;
                    const int gc = cn + (q & 1);
                    const size_t o = (size_t)rr * N + gc;
                    float v = c[i][j][q] + bp[gc];
                    v = epi_fn<EPI>(v, gc, N, silu5);
                    if (RES) v += res[o];
                    if (OBF) ((__nv_bfloat16*)op)[o] = __float2bfloat16(v);
                    else op[o] = v;
                }
            }
        }
    }
#endif
}

// ---------------- fused prep: 7 weight transposes (->bf16) + x_q round -----
#define ROUND_BLKS 8192
struct PrepTab {
    const float* src[7];
    int dst[7];
    int K[7];
    int N[7];
    int boff[8];
};

__global__ void prep_kernel(const __grid_constant__ PrepTab tab,
                            const float* __restrict__ xq,
                            __nv_bfloat16* __restrict__ xqr,
                            __nv_bfloat16* __restrict__ wT)
{
    GDC_LAUNCH();
    const int bid = blockIdx.x;
    const int tid = threadIdx.x;
    if (bid < ROUND_BLKS) {
        const int idx = bid * 1024 + tid * 4;
        const float4 v = *(const float4*)(xq + idx);
        uint32_t p0, p1;
        PKBF(p0, v.x, v.y);
        PKBF(p1, v.z, v.w);
        *(uint2*)(xqr + idx) = make_uint2(p0, p1);
        return;
    }
    const int rb = bid - ROUND_BLKS;
    int i = 0;
#pragma unroll
    for (int s = 1; s < 7; s++) if (rb >= tab.boff[s]) i = s;
    const int local = rb - tab.boff[i];
    const int K = tab.K[i], N = tab.N[i];
    const int nbx = N >> 5;
    const int n0 = (local % nbx) * 32;
    const int k0 = (local / nbx) * 32;
    const float* in = tab.src[i];
    __nv_bfloat16* out = wT + tab.dst[i];

    __shared__ float t[32][33];
    const int tx = tid & 31, ty = tid >> 5;
#pragma unroll
    for (int it = 0; it < 4; it++)
        t[ty + it * 8][tx] = in[(size_t)(k0 + ty + it * 8) * N + n0 + tx];
    __syncthreads();
#pragma unroll
    for (int it = 0; it < 4; it++)
        out[(size_t)(n0 + ty + it * 8) * K + k0 + tx] = __float2bfloat16(t[tx][ty + it * 8]);
}

// --------- fused cpe conv + LayerNorm (LN out -> bf16) ---------------------
__global__ void cpe_ln_kernel(const float* __restrict__ x,
                              const float* __restrict__ w,
                              const float* __restrict__ cb,
                              const float* __restrict__ g,
                              const float* __restrict__ b,
                              float* __restrict__ xout,
                              __nv_bfloat16* __restrict__ lnout)
{
    GDC_WAIT();
    GDC_LAUNCH();
    const int row = blockIdx.x;
    const int l = row & (LL - 1);
    const int tid = threadIdx.x;
    const int c0 = tid * 4;

    const float4 vm = ((const float4*)(x + (size_t)row * CC))[tid];
    float4 vp = make_float4(0.f, 0.f, 0.f, 0.f);
    float4 vn = make_float4(0.f, 0.f, 0.f, 0.f);
    if (l > 0)      vp = ((const float4*)(x + (size_t)(row - 1) * CC))[tid];
    if (l < LL - 1) vn = ((const float4*)(x + (size_t)(row + 1) * CC))[tid];

    const float xm[4] = { vm.x, vm.y, vm.z, vm.w };
    const float xpv[4] = { vp.x, vp.y, vp.z, vp.w };
    const float xnv[4] = { vn.x, vn.y, vn.z, vn.w };
    float o[4];
#pragma unroll
    for (int j = 0; j < 4; j++) {
        const int c = c0 + j;
        float s = cb[c] + w[c * 3 + 0] * xpv[j] + w[c * 3 + 1] * xm[j]
                        + w[c * 3 + 2] * xnv[j];
        o[j] = xm[j] + s;
    }
    *(float4*)(xout + (size_t)row * CC + c0) = *(float4*)o;

    float s  = o[0] + o[1] + o[2] + o[3];
    float sq = o[0]*o[0] + o[1]*o[1] + o[2]*o[2] + o[3]*o[3];
#pragma unroll
    for (int of = 16; of; of >>= 1) {
        s  += __shfl_xor_sync(0xffffffffu, s,  of);
        sq += __shfl_xor_sync(0xffffffffu, sq, of);
    }
    __shared__ float ssum[4], ssq[4];
    const int wd = tid >> 5;
    if ((tid & 31) == 0) { ssum[wd] = s; ssq[wd] = sq; }
    __syncthreads();
    const float tot  = ssum[0] + ssum[1] + ssum[2] + ssum[3];
    const float totq = ssq[0]  + ssq[1]  + ssq[2]  + ssq[3];
    const float mu  = tot * (1.f / CC);
    const float var = totq * (1.f / CC) - mu * mu;
    const float rs  = rsqrtf(var + 1e-5f);
    float ov[4];
#pragma unroll
    for (int j = 0; j < 4; j++)
        ov[j] = (o[j] - mu) * rs * g[c0 + j] + b[c0 + j];
    uint32_t p0, p1;
    PKBF(p0, ov[0], ov[1]);
    PKBF(p1, ov[2], ov[3]);
    *(uint2*)(lnout + (size_t)row * CC + c0) = make_uint2(p0, p1);
}

// --------- dwc (reshaped view, bf16 in), silu -> bf16, x4 ------------------
__global__ void dwc_kernel(const __nv_bfloat16* __restrict__ in,
                           const float* __restrict__ w,
                           const float* __restrict__ bias,
                           __nv_bfloat16* __restrict__ out)
{
    GDC_WAIT();
    GDC_LAUNCH();
    const int t = blockIdx.x * blockDim.x + threadIdx.x;
    const int idx = t * 4;
    const int f = idx & (LL * CC - 1);
    const int r = f >> 11;
    const int j0 = f & (LL - 1);
    const float4 v = ld_bf4(in + idx);
    const float w0 = w[r * 3], w1 = w[r * 3 + 1], w2 = w[r * 3 + 2], bb = bias[r];
    float a[6];
    a[0] = (j0 > 0) ? __bfloat162float(in[idx - 1]) : 0.f;
    a[1] = v.x; a[2] = v.y; a[3] = v.z; a[4] = v.w;
    a[5] = (j0 + 4 < LL) ? __bfloat162float(in[idx + 4]) : 0.f;
    float o[4];
#pragma unroll
    for (int jj = 0; jj < 4; jj++) {
        const int j = j0 + jj;
        float s = bb + w1 * a[jj + 1];
        if (j > 0)      s += w0 * a[jj];
        if (j < LL - 1) s += w2 * a[jj + 2];
        o[jj] = s / (1.f + __expf(-s));
    }
    uint32_t p0, p1;
    PKBF(p0, o[0], o[1]);
    PKBF(p1, o[2], o[3]);
    *(uint2*)(out + idx) = make_uint2(p0, p1);
}

// --------- kv partial: K^T V (64x64) + k colsum (kv bf16) -------------------
__global__ __launch_bounds__(256) void kvp_kernel(const __nv_bfloat16* __restrict__ kv,
                                                  float* __restrict__ kvpart,
                                                  float* __restrict__ kspart)
{
    GDC_WAIT();
    GDC_LAUNCH();
    const int chunk = blockIdx.x;
    const int bh = blockIdx.y;
    const int b = bh >> 3, h = bh & 7;
    __shared__ float ks[64][64];
    __shared__ float vs[64][64];
    const int tid = threadIdx.x;
    const int d0 = (tid >> 4) << 2, e0 = (tid & 15) << 2;
    float acc[4][4];
#pragma unroll
    for (int i = 0; i < 4; i++)
#pragma unroll
        for (int j = 0; j < 4; j++) acc[i][j] = 0.f;
    float ksum = 0.f;

    const __nv_bfloat16* kb = kv + (size_t)b * LL * (2 * CC) + h * HDIM;
    const __nv_bfloat16* vb = kb + CC;
    const int row0 = chunk * 256;
    for (int n0 = row0; n0 < row0 + 256; n0 += 64) {
#pragma unroll
        for (int i = 0; i < 4; i++) {
            int v = tid + i * 256;
            int r = v >> 4; int c = (v & 15) << 2;
            *(float4*)(&ks[r][c]) = ld_bf4(kb + (size_t)(n0 + r) * (2 * CC) + c);
            *(float4*)(&vs[r][c]) = ld_bf4(vb + (size_t)(n0 + r) * (2 * CC) + c);
        }
        __syncthreads();
        if (tid < 64) {
            float s = 0.f;
#pragma unroll 16
            for (int n = 0; n < 64; n++) s += ks[n][tid];
            ksum += s;
        }
#pragma unroll 8
        for (int n = 0; n < 64; n++) {
            float a[4], bb[4];
            *(float4*)a  = *(float4*)(&ks[n][d0]);
            *(float4*)bb = *(float4*)(&vs[n][e0]);
#pragma unroll
            for (int i = 0; i < 4; i++)
#pragma unroll
                for (int j = 0; j < 4; j++)
                    acc[i][j] = fmaf(a[i], bb[j], acc[i][j]);
        }
        __syncthreads();
    }
    float* o = kvpart + ((size_t)bh * 8 + chunk) * (HDIM * HDIM);
#pragma unroll
    for (int i = 0; i < 4; i++)
#pragma unroll
        for (int j = 0; j < 4; j++)
            o[(d0 + i) * HDIM + e0 + j] = acc[i][j];
    if (tid < 64) kspart[((size_t)bh * 8 + chunk) * HDIM + tid] = ksum;
}

__global__ void kvred_kernel(const float* __restrict__ kvpart,
                             const float* __restrict__ kspart,
                             float* __restrict__ kvmat,
                             float* __restrict__ kmean)
{
    GDC_WAIT();
    GDC_LAUNCH();
    const int bh = blockIdx.x;
    const int tid = threadIdx.x;
#pragma unroll
    for (int i = 0; i < 16; i++) {
        const int e = i * 256 + tid;
        float s = 0.f;
#pragma unroll
        for (int c = 0; c < 8; c++)
            s += kvpart[((size_t)bh * 8 + c) * (HDIM * HDIM) + e];
        kvmat[(size_t)bh * (HDIM * HDIM) + e] = s * (1.f / LL);
    }
    if (tid < 64) {
        float s = 0.f;
#pragma unroll
        for (int c = 0; c < 8; c++)
            s += kspart[((size_t)bh * 8 + c) * HDIM + tid];
        kmean[(size_t)(bh >> 3) * CC + (bh & 7) * HDIM + tid] = s;
    }
}

// --------- attention out, FUSED with lepe conv + act gate -> xab bf16 ------
__global__ __launch_bounds__(256) void attn_kernel(
    const __nv_bfloat16* __restrict__ q,
    const float* __restrict__ kvmat,
    const float* __restrict__ kmean,
    const __nv_bfloat16* __restrict__ kv,
    const __nv_bfloat16* __restrict__ act,
    const float* __restrict__ lw,
    const float* __restrict__ lb,
    __nv_bfloat16* __restrict__ xab)
{
    GDC_WAIT();
    GDC_LAUNCH();
    const int n0 = blockIdx.x * 64;
    const int h = blockIdx.y, b = blockIdx.z;
    __shared__ float kvm[64][64];
    __shared__ float qT[64][65];
    __shared__ float km[64];
    __shared__ float zs[64];
    const int tid = threadIdx.x;

    const float* kvb = kvmat + ((size_t)(b * HH + h)) * (HDIM * HDIM);
#pragma unroll
    for (int i = 0; i < 4; i++) {
        int v = tid + i * 256;
        int r = v >> 4; int c = (v & 15) << 2;
        *(float4*)(&kvm[r][c]) = *(const float4*)(kvb + (size_t)r * 64 + c);
    }
    const __nv_bfloat16* qb = q + (size_t)b * LL * CC + (size_t)n0 * CC + h * HDIM;
#pragma unroll
    for (int i = 0; i < 4; i++) {
        int v = tid + i * 256;
        int t = v >> 4; int c = (v & 15) << 2;
        float4 q4 = ld_bf4(qb + (size_t)t * CC + c);
        qT[c + 0][t] = q4.x; qT[c + 1][t] = q4.y;
        qT[c + 2][t] = q4.z; qT[c + 3][t] = q4.w;
    }
    if (tid < 64) km[tid] = kmean[(size_t)b * CC + h * HDIM + tid] * (1.f / LL);
    __syncthreads();
    if (tid < 64) {
        float dot = 0.f;
#pragma unroll 16
        for (int d = 0; d < 64; d++) dot += qT[d][tid] * km[d];
        zs[tid] = 1.f / (dot + 1e-6f);
    }
    __syncthreads();

    const int t0 = (tid >> 4) << 2, e0 = (tid & 15) << 2;
    float acc[4][4];
#pragma unroll
    for (int i = 0; i < 4; i++)
#pragma unroll
        for (int j = 0; j < 4; j++) acc[i][j] = 0.f;
#pragma unroll 8
    for (int d = 0; d < 64; d++) {
        float a[4];
#pragma unroll
        for (int i = 0; i < 4; i++) a[i] = qT[d][t0 + i];
        float bb[4];
        *(float4*)bb = *(float4*)(&kvm[d][e0]);
#pragma unroll
        for (int i = 0; i < 4; i++)
#pragma unroll
            for (int j = 0; j < 4; j++)
                acc[i][j] = fmaf(a[i], bb[j], acc[i][j]);
    }

    const int gc0 = h * HDIM + e0;
    float w0[4], w1[4], w2[4], lb4[4];
#pragma unroll
    for (int j = 0; j < 4; j++) {
        w0[j]  = lw[(gc0 + j) * 3 + 0];
        w1[j]  = lw[(gc0 + j) * 3 + 1];
        w2[j]  = lw[(gc0 + j) * 3 + 2];
        lb4[j] = lb[gc0 + j];
    }
#pragma unroll
    for (int i = 0; i < 4; i++) {
        const int n = n0 + t0 + i;
        const size_t gn = (size_t)b * LL + n;
        const __nv_bfloat16* vr = kv + gn * (2 * CC) + CC + gc0;
        const float4 vmv = ld_bf4(vr);
        float4 vpv = make_float4(0.f, 0.f, 0.f, 0.f);
        float4 vnv = make_float4(0.f, 0.f, 0.f, 0.f);
        if (n > 0)      vpv = ld_bf4(vr - 2 * CC);
        if (n < LL - 1) vnv = ld_bf4(vr + 2 * CC);
        const float4 a4 = ld_bf4(act + gn * CC + gc0);
        const float z = zs[t0 + i];
        float o[4];
        o[0] = (acc[i][0] * z + lb4[0] + w0[0] * vpv.x + w1[0] * vmv.x + w2[0] * vnv.x) * a4.x;
        o[1] = (acc[i][1] * z + lb4[1] + w0[1] * vpv.y + w1[1] * vmv.y + w2[1] * vnv.y) * a4.y;
        o[2] = (acc[i][2] * z + lb4[2] + w0[2] * vpv.z + w1[2] * vmv.z + w2[2] * vnv.z) * a4.z;
        o[3] = (acc[i][3] * z + lb4[3] + w0[3] * vpv.w + w1[3] * vmv.w + w2[3] * vnv.w) * a4.w;
        uint32_t p0, p1;
        PKBF(p0, o[0], o[1]);
        PKBF(p1, o[2], o[3]);
        *(uint2*)(xab + gn * CC + gc0) = make_uint2(p0, p1);
    }
}

// ---------------------------------------------------------------------------
typedef CUresult (*PFN_encodeTiled)(CUtensorMap*, CUtensorMapDataType, cuuint32_t,
    void*, const cuuint64_t*, const cuuint64_t*, const cuuint32_t*, const cuuint32_t*,
    CUtensorMapInterleave, CUtensorMapSwizzle, CUtensorMapL2promotion, CUtensorMapFloatOOBfill);

static void mk2db(PFN_encodeTiled fn, CUtensorMap* m, const void* p,
                  unsigned long long inner, unsigned long long outer, unsigned boxY)
{
    cuuint64_t dims[2] = { inner, outer };
    cuuint64_t st[1]   = { inner * 2 };
    cuuint32_t box[2]  = { 64, boxY };
    cuuint32_t es[2]   = { 1, 1 };
    fn(m, CU_TENSOR_MAP_DATA_TYPE_BFLOAT16, 2, (void*)p, dims, st, box, es,
       CU_TENSOR_MAP_INTERLEAVE_NONE, CU_TENSOR_MAP_SWIZZLE_128B,
       CU_TENSOR_MAP_L2_PROMOTION_L2_128B, CU_TENSOR_MAP_FLOAT_OOB_FILL_NONE);
}

// launch helper with programmatic stream serialization (PDL)
template<class K, class... A>
static void launch_pdl(dim3 g, dim3 b, size_t sm, K k, A... args)
{
    cudaLaunchConfig_t cfg = {};
    cfg.gridDim = g;
    cfg.blockDim = b;
    cfg.dynamicSmemBytes = sm;
    cudaLaunchAttribute at[1];
    at[0].id = cudaLaunchAttributeProgrammaticStreamSerialization;
    at[0].val.programmaticStreamSerializationAllowed = 1;
    cfg.attrs = at;
    cfg.numAttrs = 1;
    cudaLaunchKernelEx(&cfg, k, args...);
}

extern "C" void kernel_launch(void* const* d_in, const int* in_sizes, int n_in,
                              void* d_out, int out_size)
{
    const float* x_q    = (const float*)d_in[0];
    const float* x_kv   = (const float*)d_in[1];
    const float* cpe1_w = (const float*)d_in[2];
    const float* cpe1_b = (const float*)d_in[3];
    const float* n1_g   = (const float*)d_in[4];
    const float* n1_b   = (const float*)d_in[5];
    const float* in_w   = (const float*)d_in[6];
    const float* in_b   = (const float*)d_in[7];
    const float* act_w  = (const float*)d_in[8];
    const float* act_b  = (const float*)d_in[9];
    const float* dwc_w  = (const float*)d_in[10];
    const float* dwc_b  = (const float*)d_in[11];
    const float* q_w    = (const float*)d_in[12];
    const float* q_b    = (const float*)d_in[13];
    const float* kv_w   = (const float*)d_in[14];
    const float* kv_b   = (const float*)d_in[15];
    const float* lepe_w = (const float*)d_in[16];
    const float* lepe_b = (const float*)d_in[17];
    const float* out_w  = (const float*)d_in[18];
    const float* out_b  = (const float*)d_in[19];
    const float* cpe2_w = (const float*)d_in[20];
    const float* cpe2_b = (const float*)d_in[21];
    const float* n2_g   = (const float*)d_in[22];
    const float* n2_b   = (const float*)d_in[23];
    const float* fc1_w  = (const float*)d_in[24];
    const float* fc1_b  = (const float*)d_in[25];
    const float* fc2_w  = (const float*)d_in[26];
    const float* fc2_b  = (const float*)d_in[27];
    float* outp = (float*)d_out;

    float *p_x, *p_x2, *p_x3, *p_kvpart, *p_kspart, *p_kmean, *p_kvmat;
    __nv_bfloat16 *p_ln, *p_act, *p_xp, *p_xp2, *p_kv, *p_q, *p_xqr, *p_xab, *p_h1, *p_wT;
    cudaGetSymbolAddress((void**)&p_x,      g_x);
    cudaGetSymbolAddress((void**)&p_x2,     g_x2);
    cudaGetSymbolAddress((void**)&p_x3,     g_x3);
    cudaGetSymbolAddress((void**)&p_ln,     g_ln);
    cudaGetSymbolAddress((void**)&p_act,    g_act);
    cudaGetSymbolAddress((void**)&p_xp,     g_xp);
    cudaGetSymbolAddress((void**)&p_xp2,    g_xp2);
    cudaGetSymbolAddress((void**)&p_kv,     g_kv);
    cudaGetSymbolAddress((void**)&p_q,      g_q);
    cudaGetSymbolAddress((void**)&p_xqr,    g_xqr);
    cudaGetSymbolAddress((void**)&p_xab,    g_xab);
    cudaGetSymbolAddress((void**)&p_h1,     g_h1);
    cudaGetSymbolAddress((void**)&p_wT,     g_wT);
    cudaGetSymbolAddress((void**)&p_kvpart, g_kvpart);
    cudaGetSymbolAddress((void**)&p_kspart, g_kspart);
    cudaGetSymbolAddress((void**)&p_kmean,  g_kmean);
    cudaGetSymbolAddress((void**)&p_kvmat,  g_kvmat);

    PFN_encodeTiled enc = nullptr;
#if CUDART_VERSION >= 12050
    {
        cudaDriverEntryPointQueryResult qr;
        cudaGetDriverEntryPointByVersion("cuTensorMapEncodeTiled", (void**)&enc,
                                         12000, cudaEnableDefault, &qr);
    }
#else
    {
        cudaDriverEntryPointQueryResult qr;
        cudaGetDriverEntryPoint("cuTensorMapEncodeTiled", (void**)&enc,
                                cudaEnableDefault, &qr);
    }
#endif

    CUtensorMap tmLn, tmXqr, tmXp2, tmXab, tmH1;
    CUtensorMap tmWai, tmWq, tmWkv, tmWout, tmWfc1, tmWfc2;
    mk2db(enc, &tmLn,  p_ln,  CC, TOK, 128);
    mk2db(enc, &tmXqr, p_xqr, CC, TOK, 128);
    mk2db(enc, &tmXp2, p_xp2, CC, TOK, 128);
    mk2db(enc, &tmXab, p_xab, CC, TOK, 128);
    mk2db(enc, &tmH1,  p_h1,  MH, TOK, 128);
    mk2db(enc, &tmWai,  p_wT + WT_ACT, CC, 2 * CC, 256);
    mk2db(enc, &tmWq,   p_wT + WT_Q,   CC, CC,     256);
    mk2db(enc, &tmWkv,  p_wT + WT_KV,  CC, 2 * CC, 256);
    mk2db(enc, &tmWout, p_wT + WT_OUT, CC, CC,     256);
    mk2db(enc, &tmWfc1, p_wT + WT_FC1, CC, MH,     256);
    mk2db(enc, &tmWfc2, p_wT + WT_FC2, MH, CC,     256);

    cudaFuncSetAttribute(tc_gemm<5, false, true >, cudaFuncAttributeMaxDynamicSharedMemorySize, SM_SZ);
    cudaFuncSetAttribute(tc_gemm<4, false, true >, cudaFuncAttributeMaxDynamicSharedMemorySize, SM_SZ);
    cudaFuncSetAttribute(tc_gemm<2, false, true >, cudaFuncAttributeMaxDynamicSharedMemorySize, SM_SZ);
    cudaFuncSetAttribute(tc_gemm<0, true,  false>, cudaFuncAttributeMaxDynamicSharedMemorySize, SM_SZ);
    cudaFuncSetAttribute(tc_gemm<3, false, true >, cudaFuncAttributeMaxDynamicSharedMemorySize, SM_SZ);

    const int M = TOK;
    const int VEC_BLOCKS = (TOK * CC / 4) / 256;
    const dim3 G2(2, M / 128), G4(4, M / 128), G8(8, M / 128);
    const dim3 B256(256), B128(128);

    // fused prep: 7 transposes (->bf16) + x_q round (first kernel, plain launch)
    PrepTab tab;
    const float* srcs[7] = { act_w, in_w, q_w, kv_w, out_w, fc1_w, fc2_w };
    const int dsts[7] = { WT_ACT, WT_IN, WT_Q, WT_KV, WT_OUT, WT_FC1, WT_FC2 };
    const int Ks[7] = { CC, CC, CC, CC, CC, CC, MH };
    const int Ns[7] = { CC, CC, CC, 2*CC, CC, MH, CC };
    int off = 0;
    for (int i = 0; i < 7; i++) {
        tab.src[i] = srcs[i]; tab.dst[i] = dsts[i];
        tab.K[i] = Ks[i]; tab.N[i] = Ns[i];
        tab.boff[i] = off;
        off += (Ns[i] >> 5) * (Ks[i] >> 5);
    }
    tab.boff[7] = off;
    prep_kernel<<<ROUND_BLKS + off, 256>>>(tab, x_q, p_xqr, p_wT);

    // 1+2. x = x_kv + cpe1(x_kv); ln = LN1(x) (bf16)
    launch_pdl(dim3(TOK), B128, 0, cpe_ln_kernel,
               x_kv, cpe1_w, cpe1_b, n1_g, n1_b, p_x, p_ln);
    // 3. q = bf16(elu(x_q @ q_w + b) + 1)
    launch_pdl(G2, B256, (size_t)SM_SZ, tc_gemm<2, false, true>,
               tmXqr, tmWq, q_b, (const float*)nullptr, (const float*)nullptr,
               (float*)p_q, (float*)nullptr, (int)CC, (int)CC);
    // 4+5. act = bf16(silu(ln@act_w+b)) ; xp = bf16(ln@in_w+b)
    launch_pdl(G4, B256, (size_t)SM_SZ, tc_gemm<5, false, true>,
               tmLn, tmWai, act_b, in_b, (const float*)nullptr,
               (float*)p_act, (float*)p_xp, (int)CC, (int)CC);
    // 6. xp2 = bf16(silu(dwconv(reshape(xp))))
    launch_pdl(dim3(VEC_BLOCKS), B256, 0, dwc_kernel,
               (const __nv_bfloat16*)p_xp, dwc_w, dwc_b, p_xp2);
    // 7. kv = bf16(xp2 @ kv_w + b); elu+1 on k half
    launch_pdl(G4, B256, (size_t)SM_SZ, tc_gemm<4, false, true>,
               tmXp2, tmWkv, kv_b, (const float*)nullptr, (const float*)nullptr,
               (float*)p_kv, (float*)nullptr, (int)(2 * CC), (int)CC);
    // 8+9. kv_mat + k_mean
    launch_pdl(dim3(8, BB * HH), B256, 0, kvp_kernel,
               (const __nv_bfloat16*)p_kv, p_kvpart, p_kspart);
    launch_pdl(dim3(BB * HH), B256, 0, kvred_kernel,
               (const float*)p_kvpart, (const float*)p_kspart, p_kvmat, p_kmean);
    // 10. attention out + lepe + act gate (fused) -> xab bf16
    launch_pdl(dim3(LL / 64, HH, BB), B256, 0, attn_kernel,
               (const __nv_bfloat16*)p_q, (const float*)p_kvmat, (const float*)p_kmean,
               (const __nv_bfloat16*)p_kv, (const __nv_bfloat16*)p_act,
               lepe_w, lepe_b, p_xab);
    // 11. x2 = shortcut + xab @ out_w + b
    launch_pdl(G2, B256, (size_t)SM_SZ, tc_gemm<0, true, false>,
               tmXab, tmWout, out_b, (const float*)nullptr, (const float*)p_x,
               p_x2, (float*)nullptr, (int)CC, (int)CC);
    // 12+13. x3 = x2 + cpe2(x2); ln = LN2(x3) (bf16)
    launch_pdl(dim3(TOK), B128, 0, cpe_ln_kernel,
               (const float*)p_x2, cpe2_w, cpe2_b, n2_g, n2_b, p_x3, p_ln);
    // 14. h1 = bf16(gelu(ln @ fc1_w + b))
    launch_pdl(G8, B256, (size_t)SM_SZ, tc_gemm<3, false, true>,
               tmLn, tmWfc1, fc1_b, (const float*)nullptr, (const float*)nullptr,
               (float*)p_h1, (float*)nullptr, (int)MH, (int)CC);
    // 15. out = x3 + h1 @ fc2_w + b (fp32)
    launch_pdl(G2, B256, (size_t)SM_SZ, tc_gemm<0, true, false>,
               tmH1, tmWfc2, fc2_b, (const float*)nullptr, (const float*)p_x3,
               outp, (float*)nullptr, (int)CC, (int)MH);
}